// round 14
// baseline (speedup 1.0000x reference)
#include <cuda_runtime.h>
#include <cuda_fp16.h>
#include <cstdint>

// ---------------------------------------------------------------------------
// Problem constants
// ---------------------------------------------------------------------------
#define B_ 2
#define S_ 2048
#define H_ 16
#define D_ 128
#define HID_ 2048
#define M_ (B_ * S_)   // 4096

// Scratch (device globals — allocation-free per harness rules)
__device__ float g_q[(size_t)B_ * H_ * S_ * D_];   // fp32 Q pre-rope [b,h,s,d]
__device__ float g_k[(size_t)B_ * H_ * S_ * D_];   // fp32 K pre-rope

// fp16 buffers. Activations split hi/lo; weights hi only (2-term emulation).
__device__ __half g_xhi[(size_t)M_ * HID_];
__device__ __half g_xlo[(size_t)M_ * HID_];
__device__ __half g_bhi[(size_t)4 * HID_ * HID_];

// fp16 attention operands [b,h,s,d]: Q split hi/lo; K, V hi only.
#define QKV_ELEMS ((size_t)B_ * H_ * S_ * D_)
__device__ __half g_qh[QKV_ELEMS];
__device__ __half g_ql[QKV_ELEMS];
__device__ __half g_kh[QKV_ELEMS];
__device__ __half g_vh[QKV_ELEMS];

// ---------------------------------------------------------------------------
// PTX helpers (non-'a' features only)
// ---------------------------------------------------------------------------
__device__ __forceinline__ uint32_t smem_u32(const void* p) {
    uint32_t a;
    asm("{ .reg .u64 t; cvta.to.shared.u64 t, %1; cvt.u32.u64 %0, t; }"
        : "=r"(a) : "l"(p));
    return a;
}
__device__ __forceinline__ void cpa16(uint32_t s, const void* g) {
    asm volatile("cp.async.cg.shared.global [%0], [%1], 16;" :: "r"(s), "l"(g));
}
#define CP_COMMIT() asm volatile("cp.async.commit_group;" ::: "memory")
#define CP_WAIT0()  asm volatile("cp.async.wait_group 0;" ::: "memory")
#define CP_WAIT1()  asm volatile("cp.async.wait_group 1;" ::: "memory")

#define LDSM4(r, addr)                                                        \
    asm volatile("ldmatrix.sync.aligned.m8n8.x4.shared.b16 {%0,%1,%2,%3}, [%4];" \
                 : "=r"((r)[0]), "=r"((r)[1]), "=r"((r)[2]), "=r"((r)[3])     \
                 : "r"(addr))
#define LDSM4T(r, addr)                                                       \
    asm volatile("ldmatrix.sync.aligned.m8n8.x4.trans.shared.b16 {%0,%1,%2,%3}, [%4];" \
                 : "=r"((r)[0]), "=r"((r)[1]), "=r"((r)[2]), "=r"((r)[3])     \
                 : "r"(addr))

#define MMAF32(d, a, b)                                                       \
    asm volatile(                                                             \
        "mma.sync.aligned.m16n8k16.row.col.f32.f16.f16.f32 "                  \
        "{%0,%1,%2,%3}, {%4,%5,%6,%7}, {%8,%9}, {%0,%1,%2,%3};"               \
        : "+f"((d)[0]), "+f"((d)[1]), "+f"((d)[2]), "+f"((d)[3])              \
        : "r"((a)[0]), "r"((a)[1]), "r"((a)[2]), "r"((a)[3]),                 \
          "r"((b)[0]), "r"((b)[1]))

__device__ __forceinline__ float2 h2f2(uint32_t u) {
    __half2 h = *(__half2*)&u;
    return __half22float2(h);
}
__device__ __forceinline__ uint32_t f2h2(float x, float y) {
    __half2 h = __float22half2_rn(make_float2(x, y));
    return *(uint32_t*)&h;
}

// fp32 -> fp16 hi/lo split
__device__ __forceinline__ void split1(float x, unsigned short& h, unsigned short& l) {
    __half hb = __float2half_rn(x);
    __half lb = __float2half_rn(x - __half2float(hb));
    h = __half_as_ushort(hb);
    l = __half_as_ushort(lb);
}

// ---------------------------------------------------------------------------
// Activations: X [M,K] fp32 -> g_xhi/g_xlo fp16.
// ---------------------------------------------------------------------------
__global__ void asplit_kernel(const float* __restrict__ src) {
    size_t i = (size_t)blockIdx.x * 256 + threadIdx.x;
    float4 v = ((const float4*)src)[i];
    ushort4 h, l;
    split1(v.x, h.x, l.x);
    split1(v.y, h.y, l.y);
    split1(v.z, h.z, l.z);
    split1(v.w, h.w, l.w);
    ((ushort4*)g_xhi)[i] = h;
    ((ushort4*)g_xlo)[i] = l;
}

// All 4 weights in one launch: W [K,N] fp32 -> g_bhi slot z, [N,K] fp16 hi.
__global__ void wsplit_kernel(const float* __restrict__ W0,
                              const float* __restrict__ W1,
                              const float* __restrict__ W2,
                              const float* __restrict__ W3) {
    __shared__ float ts[32][33];
    const int tx = threadIdx.x, ty = threadIdx.y;
    const int n0 = blockIdx.x * 32, k0 = blockIdx.y * 32;
    const int widx = blockIdx.z;
    const float* W = (widx == 0) ? W0 : (widx == 1) ? W1 : (widx == 2) ? W2 : W3;
    __half* bh = g_bhi + (size_t)widx * HID_ * HID_;
#pragma unroll
    for (int i = 0; i < 4; i++)
        ts[ty + 8 * i][tx] = W[(size_t)(k0 + ty + 8 * i) * HID_ + n0 + tx];
    __syncthreads();
#pragma unroll
    for (int i = 0; i < 4; i++) {
        int n = n0 + ty + 8 * i;
        int k = k0 + tx;
        bh[(size_t)n * HID_ + k] = __float2half_rn(ts[tx][ty + 8 * i]);
    }
}

// ---------------------------------------------------------------------------
// mma.sync fp16x2 GEMM. CTA tile 128x256, 8 warps, warp tile 32x128
// (4m x 2n). Doubles mma per smem byte vs 128x128 (smem BW was the limiter).
// 3-stage cp.async pipeline, one sync per chunk, 1 CTA/SM.
// MODE==1: fused QKV (blockIdx.x = widx*8 + nb; warp head = nb*2 + wn).
// MODE==0: O projection.
// ---------------------------------------------------------------------------
#define PITCH 144
#define ASTG (128 * PITCH)            // 18432 per A matrix (hi or lo)
#define BSTG (256 * PITCH)            // 36864
#define STGB (2 * ASTG + BSTG)        // 73728 per stage
#define GEMM_SMEM (3 * STGB)          // 221184
#define NCH (HID_ / 64)               // 32

template <int MODE>
__global__ __launch_bounds__(256, 1) void mma_gemm(float* __restrict__ Cout) {
    extern __shared__ char dsm[];
    const uint32_t sb = smem_u32(dsm);
    const int t = threadIdx.x;
    const int lane = t & 31, wid = t >> 5;
    const int wm = wid & 3, wn = wid >> 2;
    const int m0 = blockIdx.y * 128;
    const int widx = (MODE == 1) ? (blockIdx.x >> 3) : 3;
    const int nblk = (MODE == 1) ? (blockIdx.x & 7) : blockIdx.x;
    const int n0 = nblk * 256;

    const __half* __restrict__ AH = g_xhi;
    const __half* __restrict__ AL = g_xlo;
    const __half* __restrict__ BH = g_bhi + (size_t)widx * HID_ * HID_;

    float acc[2][16][4];
#pragma unroll
    for (int i = 0; i < 2; i++)
#pragma unroll
        for (int j = 0; j < 16; j++)
#pragma unroll
            for (int k = 0; k < 4; k++) acc[i][j][k] = 0.f;

    const int lrow = t >> 3;          // 0..31 (with j*32: 0..127 / 0..255)
    const int lch = t & 7;

    // prologue: stages 0,1
#pragma unroll
    for (int s = 0; s < 2; s++) {
        const uint32_t base = sb + s * STGB;
        const int k0 = s * 64;
#pragma unroll
        for (int j = 0; j < 4; j++) {     // A rows 0..127 (hi + lo)
            int row = lrow + j * 32;
            uint32_t sa = base + row * PITCH + lch * 16;
            size_t ga = (size_t)(m0 + row) * HID_ + k0 + lch * 8;
            cpa16(sa, AH + ga);
            cpa16(sa + ASTG, AL + ga);
        }
#pragma unroll
        for (int j = 0; j < 8; j++) {     // B rows 0..255
            int row = lrow + j * 32;
            uint32_t sa = base + 2 * ASTG + row * PITCH + lch * 16;
            size_t gb = (size_t)(n0 + row) * HID_ + k0 + lch * 8;
            cpa16(sa, BH + gb);
        }
        CP_COMMIT();
    }

    const uint32_t lm_a_off =
        (uint32_t)((wm * 32 + (lane & 15)) * PITCH + (lane >> 4) * 16);
    const uint32_t lm_b_off =
        (uint32_t)((wn * 128 + (lane & 15)) * PITCH + (lane >> 4) * 16);

    int bufn = 0;
    int pbuf = 2;
    for (int c = 0; c < NCH; c++) {
        CP_WAIT1();           // chunk c resident (only c+1's group may pend)
        __syncthreads();      // visibility + all warps done with buf (c+2)%3

        if (c + 2 < NCH) {
            const uint32_t base = sb + pbuf * STGB;
            const int k0 = (c + 2) * 64;
#pragma unroll
            for (int j = 0; j < 4; j++) {
                int row = lrow + j * 32;
                uint32_t sa = base + row * PITCH + lch * 16;
                size_t ga = (size_t)(m0 + row) * HID_ + k0 + lch * 8;
                cpa16(sa, AH + ga);
                cpa16(sa + ASTG, AL + ga);
            }
#pragma unroll
            for (int j = 0; j < 8; j++) {
                int row = lrow + j * 32;
                uint32_t sa = base + 2 * ASTG + row * PITCH + lch * 16;
                size_t gb = (size_t)(n0 + row) * HID_ + k0 + lch * 8;
                cpa16(sa, BH + gb);
            }
        }
        CP_COMMIT();          // (possibly empty) group every iteration

        const uint32_t cb = sb + bufn * STGB;
#pragma unroll
        for (int ks = 0; ks < 4; ks++) {
            uint32_t ah[2][4], al[2][4];
#pragma unroll
            for (int mt = 0; mt < 2; mt++) {
                uint32_t addr = cb + lm_a_off + mt * (16 * PITCH) + ks * 32;
                LDSM4(ah[mt], addr);
                LDSM4(al[mt], addr + ASTG);
            }
#pragma unroll
            for (int np = 0; np < 8; np++) {   // B frags transient
                uint32_t addr = cb + 2 * ASTG + lm_b_off + np * (16 * PITCH) + ks * 32;
                uint32_t r[4];
                LDSM4(r, addr);
                uint32_t b0[2] = {r[0], r[2]};
                uint32_t b1[2] = {r[1], r[3]};
#pragma unroll
                for (int mt = 0; mt < 2; mt++) {
                    MMAF32(acc[mt][2 * np], ah[mt], b0);
                    MMAF32(acc[mt][2 * np], al[mt], b0);
                    MMAF32(acc[mt][2 * np + 1], ah[mt], b1);
                    MMAF32(acc[mt][2 * np + 1], al[mt], b1);
                }
            }
        }
        bufn = (bufn == 2) ? 0 : bufn + 1;
        pbuf = (pbuf == 2) ? 0 : pbuf + 1;
    }

    // Epilogue: warp covers cols wn*128 .. +127 (one head when MODE==1)
    const int qrow = lane >> 2;
    const int qcol = (lane & 3) * 2;
#pragma unroll
    for (int mt = 0; mt < 2; mt++) {
#pragma unroll
        for (int half_ = 0; half_ < 2; half_++) {
            const int m = m0 + wm * 32 + mt * 16 + qrow + half_ * 8;
            if (MODE == 1) {
                const int head = nblk * 2 + wn;
                int b_ = m >> 11, s_ = m & (S_ - 1);
                size_t base = (((size_t)b_ * H_ + head) * S_ + s_) * D_;
                if (widx == 2) {
#pragma unroll
                    for (int nt = 0; nt < 16; nt++) {
                        int col = nt * 8 + qcol;
                        *(uint32_t*)(g_vh + base + col) =
                            f2h2(acc[mt][nt][half_ * 2], acc[mt][nt][half_ * 2 + 1]);
                    }
                } else {
                    float* dst = (widx == 0) ? g_q : g_k;
#pragma unroll
                    for (int nt = 0; nt < 16; nt++) {
                        int col = nt * 8 + qcol;
                        *(float2*)(dst + base + col) =
                            make_float2(acc[mt][nt][half_ * 2], acc[mt][nt][half_ * 2 + 1]);
                    }
                }
            } else {
                size_t base = (size_t)m * HID_ + n0 + wn * 128;
#pragma unroll
                for (int nt = 0; nt < 16; nt++) {
                    int col = nt * 8 + qcol;
                    *(float2*)(Cout + base + col) =
                        make_float2(acc[mt][nt][half_ * 2], acc[mt][nt][half_ * 2 + 1]);
                }
            }
        }
    }
}

// ---------------------------------------------------------------------------
// RoPE: read fp32 g_q/g_k, rotate, emit qh/ql (fp16 split) and kh (round).
// ---------------------------------------------------------------------------
__global__ void rope_split_kernel(const float* __restrict__ cosb,
                                  const float* __restrict__ sinb) {
    int tid = blockIdx.x * 256 + threadIdx.x;
    int d = tid & 63;
    int s = (tid >> 6) & (S_ - 1);
    int bh = tid >> 17;
    size_t base = ((size_t)bh * S_ + s) * D_;
    float c0 = cosb[s * D_ + d], c1 = cosb[s * D_ + d + 64];
    float s0 = sinb[s * D_ + d], s1 = sinb[s * D_ + d + 64];

    float q0 = g_q[base + d], q1 = g_q[base + d + 64];
    float k0 = g_k[base + d], k1 = g_k[base + d + 64];
    float qa = q0 * c0 - q1 * s0;
    float qb = q1 * c1 + q0 * s1;
    float ka = k0 * c0 - k1 * s0;
    float kb = k1 * c1 + k0 * s1;

    unsigned short h, l;
    split1(qa, h, l);
    g_qh[base + d] = __ushort_as_half(h);
    g_ql[base + d] = __ushort_as_half(l);
    split1(qb, h, l);
    g_qh[base + d + 64] = __ushort_as_half(h);
    g_ql[base + d + 64] = __ushort_as_half(l);
    g_kh[base + d] = __float2half_rn(ka);
    g_kh[base + d + 64] = __float2half_rn(kb);
}

// ---------------------------------------------------------------------------
// Flash attention (R13 structure, one sync per iteration).
// CTA = 64 q-rows, 128 threads, K/V 64-key tiles double-buffered, 2 CTAs/SM.
// ---------------------------------------------------------------------------
#define AP    272
#define AMAT2 (64 * AP)               // 17408
#define ATTN_SMEM (6 * AMAT2)         // 104448
#define KT_   64
#define NKT   (S_ / KT_)              // 32

__global__ __launch_bounds__(128, 2) void attn_mma_kernel() {
    extern __shared__ char sm8[];
    const uint32_t sb = smem_u32(sm8);
    const uint32_t Qh = sb, Ql = sb + AMAT2;

    const int t = threadIdx.x, lane = t & 31, wid = t >> 5;
    const int bh = blockIdx.y;
    const int q0 = blockIdx.x * 64;
    const size_t qoff = ((size_t)bh * S_ + q0) * D_;
    const size_t koff = (size_t)bh * S_ * D_;

    const int lrow = t >> 4;
    const int lch = t & 15;

    // prologue: Q(hi,lo) + K0 + V0 in ONE group
    {
        const uint32_t K0 = sb + 2 * AMAT2, V0 = sb + 4 * AMAT2;
#pragma unroll
        for (int j = 0; j < 8; j++) {
            int row = lrow + j * 8;
            uint32_t so = (uint32_t)(row * AP + lch * 16);
            size_t gq = qoff + (size_t)row * D_ + lch * 8;
            size_t gk = koff + (size_t)row * D_ + lch * 8;
            cpa16(Qh + so, g_qh + gq);
            cpa16(Ql + so, g_ql + gq);
            cpa16(K0 + so, g_kh + gk);
            cpa16(V0 + so, g_vh + gk);
        }
        CP_COMMIT();
    }

    float sa[8][4];
    float oa[16][4];
#pragma unroll
    for (int i = 0; i < 16; i++)
#pragma unroll
        for (int j = 0; j < 4; j++) oa[i][j] = 0.f;
    float m0r = -1e30f, m1r = -1e30f, l0r = 0.f, l1r = 0.f;

    const float scale = 0.088388347648318447f;
    const uint32_t a_off =
        (uint32_t)((wid * 16 + (lane & 15)) * AP + (lane >> 4) * 16);
    const uint32_t lm_lo = (uint32_t)((lane & 15) * AP + (lane >> 4) * 16);

    for (int kt = 0; kt < NKT; kt++) {
        CP_WAIT0();           // chunk kt resident (this thread's copies)
        __syncthreads();      // visibility + all done reading buf (kt+1)&1

        // prefetch tile kt+1 (safe: that buffer last read in iter kt-1)
        if (kt + 1 < NKT) {
            const uint32_t Kn = sb + (2 + ((kt + 1) & 1)) * AMAT2;
            const uint32_t Vn = sb + (4 + ((kt + 1) & 1)) * AMAT2;
#pragma unroll
            for (int j = 0; j < 8; j++) {
                int row = lrow + j * 8;
                uint32_t so = (uint32_t)(row * AP + lch * 16);
                size_t gk = koff + (size_t)((kt + 1) * KT_ + row) * D_ + lch * 8;
                cpa16(Kn + so, g_kh + gk);
                cpa16(Vn + so, g_vh + gk);
            }
        }
        CP_COMMIT();

        const uint32_t Kc = sb + (2 + (kt & 1)) * AMAT2;
        const uint32_t Vc = sb + (4 + (kt & 1)) * AMAT2;

#pragma unroll
        for (int i = 0; i < 8; i++)
#pragma unroll
            for (int j = 0; j < 4; j++) sa[i][j] = 0.f;

        // ---- S = Q K^T (64 keys) ----
#pragma unroll
        for (int ks = 0; ks < 8; ks++) {
            uint32_t qh[4], ql[4];
            LDSM4(qh, Qh + a_off + ks * 32);
            LDSM4(ql, Ql + a_off + ks * 32);
            uint32_t kA[4][2], kB[4][2];
#pragma unroll
            for (int np = 0; np < 4; np++) {
                uint32_t r[4];
                LDSM4(r, Kc + lm_lo + (uint32_t)(np * 16 * AP) + ks * 32);
                kA[np][0] = r[0]; kB[np][0] = r[1];
                kA[np][1] = r[2]; kB[np][1] = r[3];
            }
#pragma unroll
            for (int np = 0; np < 4; np++) {
                MMAF32(sa[2 * np], qh, kA[np]);
                MMAF32(sa[2 * np + 1], qh, kB[np]);
            }
#pragma unroll
            for (int np = 0; np < 4; np++) {
                MMAF32(sa[2 * np], ql, kA[np]);
                MMAF32(sa[2 * np + 1], ql, kB[np]);
            }
        }

        // ---- online softmax ----
        float rm0 = -1e30f, rm1 = -1e30f;
#pragma unroll
        for (int nt = 0; nt < 8; nt++) {
            rm0 = fmaxf(rm0, fmaxf(sa[nt][0], sa[nt][1]));
            rm1 = fmaxf(rm1, fmaxf(sa[nt][2], sa[nt][3]));
        }
#pragma unroll
        for (int off = 1; off <= 2; off <<= 1) {
            rm0 = fmaxf(rm0, __shfl_xor_sync(0xffffffffu, rm0, off));
            rm1 = fmaxf(rm1, __shfl_xor_sync(0xffffffffu, rm1, off));
        }
        float mn0 = fmaxf(m0r, rm0 * scale);
        float mn1 = fmaxf(m1r, rm1 * scale);
        float al0 = __expf(m0r - mn0);
        float al1 = __expf(m1r - mn1);
        m0r = mn0;
        m1r = mn1;
        float rs0 = 0.f, rs1 = 0.f;
#pragma unroll
        for (int nt = 0; nt < 8; nt++) {
            float p0 = __expf(fmaf(sa[nt][0], scale, -mn0));
            float p1 = __expf(fmaf(sa[nt][1], scale, -mn0));
            float p2 = __expf(fmaf(sa[nt][2], scale, -mn1));
            float p3 = __expf(fmaf(sa[nt][3], scale, -mn1));
            sa[nt][0] = p0; sa[nt][1] = p1; sa[nt][2] = p2; sa[nt][3] = p3;
            rs0 += p0 + p1;
            rs1 += p2 + p3;
        }
#pragma unroll
        for (int off = 1; off <= 2; off <<= 1) {
            rs0 += __shfl_xor_sync(0xffffffffu, rs0, off);
            rs1 += __shfl_xor_sync(0xffffffffu, rs1, off);
        }
        l0r = l0r * al0 + rs0;
        l1r = l1r * al1 + rs1;
#pragma unroll
        for (int nt = 0; nt < 16; nt++) {
            oa[nt][0] *= al0;
            oa[nt][1] *= al0;
            oa[nt][2] *= al1;
            oa[nt][3] *= al1;
        }

        // ---- O += P V ----
#pragma unroll
        for (int ks = 0; ks < 4; ks++) {
            uint32_t aH[4], aL[4];
#pragma unroll
            for (int g = 0; g < 2; g++) {
                const int tt = 2 * ks + g;
                float x0 = sa[tt][0], y0 = sa[tt][1];
                float x1 = sa[tt][2], y1 = sa[tt][3];
                uint32_t h0 = f2h2(x0, y0);
                uint32_t h1 = f2h2(x1, y1);
                float2 b0 = h2f2(h0);
                float2 b1 = h2f2(h1);
                aH[2 * g]     = h0;
                aH[2 * g + 1] = h1;
                aL[2 * g]     = f2h2(x0 - b0.x, y0 - b0.y);
                aL[2 * g + 1] = f2h2(x1 - b1.x, y1 - b1.y);
            }
            const uint32_t vbase = lm_lo + (uint32_t)(ks * 16 * AP);
#pragma unroll
            for (int h2 = 0; h2 < 2; h2++) {
                uint32_t vA[4][2], vB[4][2];
#pragma unroll
                for (int j = 0; j < 4; j++) {
                    const int np = h2 * 4 + j;
                    uint32_t r[4];
                    LDSM4T(r, Vc + vbase + np * 32);
                    vA[j][0] = r[0]; vA[j][1] = r[1];
                    vB[j][0] = r[2]; vB[j][1] = r[3];
                }
#pragma unroll
                for (int j = 0; j < 4; j++) {
                    const int np = h2 * 4 + j;
                    MMAF32(oa[2 * np], aH, vA[j]);
                    MMAF32(oa[2 * np + 1], aH, vB[j]);
                }
#pragma unroll
                for (int j = 0; j < 4; j++) {
                    const int np = h2 * 4 + j;
                    MMAF32(oa[2 * np], aL, vA[j]);
                    MMAF32(oa[2 * np + 1], aL, vB[j]);
                }
            }
        }
    }

    // ---- finalize: write xhi/xlo fp16 splits of attn output directly ----
    const int b_ = bh >> 4, h = bh & 15;
    const int row0 = q0 + wid * 16 + (lane >> 2);
    const float inv0 = 1.0f / l0r, inv1 = 1.0f / l1r;
    const size_t base0 = ((size_t)b_ * S_ + row0) * HID_ + h * D_;
    const size_t base1 = ((size_t)b_ * S_ + row0 + 8) * HID_ + h * D_;
    const int col0 = (lane & 3) * 2;
#pragma unroll
    for (int nt = 0; nt < 16; nt++) {
        int col = 8 * nt + col0;
        float x0 = oa[nt][0] * inv0, y0 = oa[nt][1] * inv0;
        float x1 = oa[nt][2] * inv1, y1 = oa[nt][3] * inv1;
        unsigned short hx, lx, hy, ly;
        split1(x0, hx, lx);
        split1(y0, hy, ly);
        *(uint32_t*)(g_xhi + base0 + col) = (uint32_t)hx | ((uint32_t)hy << 16);
        *(uint32_t*)(g_xlo + base0 + col) = (uint32_t)lx | ((uint32_t)ly << 16);
        split1(x1, hx, lx);
        split1(y1, hy, ly);
        *(uint32_t*)(g_xhi + base1 + col) = (uint32_t)hx | ((uint32_t)hy << 16);
        *(uint32_t*)(g_xlo + base1 + col) = (uint32_t)lx | ((uint32_t)ly << 16);
    }
}

// ---------------------------------------------------------------------------
// Launch
// ---------------------------------------------------------------------------
extern "C" void kernel_launch(void* const* d_in, const int* in_sizes, int n_in,
                              void* d_out, int out_size) {
    const float* X = (const float*)d_in[0];
    const float* cosb = (const float*)d_in[1];
    const float* sinb = (const float*)d_in[2];
    const float* Wq = (const float*)d_in[3];
    const float* Wk = (const float*)d_in[4];
    const float* Wv = (const float*)d_in[5];
    const float* Wo = (const float*)d_in[6];
    float* out = (float*)d_out;

    cudaFuncSetAttribute(mma_gemm<0>, cudaFuncAttributeMaxDynamicSharedMemorySize, GEMM_SMEM);
    cudaFuncSetAttribute(mma_gemm<1>, cudaFuncAttributeMaxDynamicSharedMemorySize, GEMM_SMEM);
    cudaFuncSetAttribute(attn_mma_kernel, cudaFuncAttributeMaxDynamicSharedMemorySize, ATTN_SMEM);

    // all weight conversions in one launch; activations split
    wsplit_kernel<<<dim3(64, 64, 4), dim3(32, 8)>>>(Wq, Wk, Wv, Wo);
    asplit_kernel<<<(M_ * HID_ / 4) / 256, 256>>>(X);

    // fused QKV projection: 3 weights x 8 n-tiles (256-wide), 32 m-tiles
    mma_gemm<1><<<dim3(24, M_ / 128), 256, GEMM_SMEM>>>(nullptr);

    rope_split_kernel<<<(B_ * H_ * S_ * 64) / 256, 256>>>(cosb, sinb);

    // attention: 64 q-rows per CTA, 128 threads, 2 CTAs/SM
    attn_mma_kernel<<<dim3(S_ / 64, B_ * H_), 128, ATTN_SMEM>>>();

    // O projection: 8 n-tiles x 32 m-tiles
    mma_gemm<0><<<dim3(HID_ / 256, M_ / 128), 256, GEMM_SMEM>>>(out);
}

// round 15
// speedup vs baseline: 1.0168x; 1.0168x over previous
#include <cuda_runtime.h>
#include <cuda_fp16.h>
#include <cstdint>

// ---------------------------------------------------------------------------
// Problem constants
// ---------------------------------------------------------------------------
#define B_ 2
#define S_ 2048
#define H_ 16
#define D_ 128
#define HID_ 2048
#define M_ (B_ * S_)   // 4096

// Scratch (device globals — allocation-free per harness rules)
__device__ float g_q[(size_t)B_ * H_ * S_ * D_];   // fp32 Q pre-rope [b,h,s,d]
__device__ float g_k[(size_t)B_ * H_ * S_ * D_];   // fp32 K pre-rope

// fp16 buffers. Activations split hi/lo; weights hi only (2-term emulation).
__device__ __half g_xhi[(size_t)M_ * HID_];
__device__ __half g_xlo[(size_t)M_ * HID_];
__device__ __half g_bhi[(size_t)4 * HID_ * HID_];

// fp16 attention operands [b,h,s,d]: Q split hi/lo; K, V hi only.
#define QKV_ELEMS ((size_t)B_ * H_ * S_ * D_)
__device__ __half g_qh[QKV_ELEMS];
__device__ __half g_ql[QKV_ELEMS];
__device__ __half g_kh[QKV_ELEMS];
__device__ __half g_vh[QKV_ELEMS];

// ---------------------------------------------------------------------------
// PTX helpers (non-'a' features only)
// ---------------------------------------------------------------------------
__device__ __forceinline__ uint32_t smem_u32(const void* p) {
    uint32_t a;
    asm("{ .reg .u64 t; cvta.to.shared.u64 t, %1; cvt.u32.u64 %0, t; }"
        : "=r"(a) : "l"(p));
    return a;
}
__device__ __forceinline__ void cpa16(uint32_t s, const void* g) {
    asm volatile("cp.async.cg.shared.global [%0], [%1], 16;" :: "r"(s), "l"(g));
}
#define CP_COMMIT() asm volatile("cp.async.commit_group;" ::: "memory")
#define CP_WAIT0()  asm volatile("cp.async.wait_group 0;" ::: "memory")
#define CP_WAIT1()  asm volatile("cp.async.wait_group 1;" ::: "memory")

#define LDSM4(r, addr)                                                        \
    asm volatile("ldmatrix.sync.aligned.m8n8.x4.shared.b16 {%0,%1,%2,%3}, [%4];" \
                 : "=r"((r)[0]), "=r"((r)[1]), "=r"((r)[2]), "=r"((r)[3])     \
                 : "r"(addr))
#define LDSM4T(r, addr)                                                       \
    asm volatile("ldmatrix.sync.aligned.m8n8.x4.trans.shared.b16 {%0,%1,%2,%3}, [%4];" \
                 : "=r"((r)[0]), "=r"((r)[1]), "=r"((r)[2]), "=r"((r)[3])     \
                 : "r"(addr))

#define MMAF32(d, a, b)                                                       \
    asm volatile(                                                             \
        "mma.sync.aligned.m16n8k16.row.col.f32.f16.f16.f32 "                  \
        "{%0,%1,%2,%3}, {%4,%5,%6,%7}, {%8,%9}, {%0,%1,%2,%3};"               \
        : "+f"((d)[0]), "+f"((d)[1]), "+f"((d)[2]), "+f"((d)[3])              \
        : "r"((a)[0]), "r"((a)[1]), "r"((a)[2]), "r"((a)[3]),                 \
          "r"((b)[0]), "r"((b)[1]))

__device__ __forceinline__ float2 h2f2(uint32_t u) {
    __half2 h = *(__half2*)&u;
    return __half22float2(h);
}
__device__ __forceinline__ uint32_t f2h2(float x, float y) {
    __half2 h = __float22half2_rn(make_float2(x, y));
    return *(uint32_t*)&h;
}

// fp32 -> fp16 hi/lo split
__device__ __forceinline__ void split1(float x, unsigned short& h, unsigned short& l) {
    __half hb = __float2half_rn(x);
    __half lb = __float2half_rn(x - __half2float(hb));
    h = __half_as_ushort(hb);
    l = __half_as_ushort(lb);
}

// ---------------------------------------------------------------------------
// Activations: X [M,K] fp32 -> g_xhi/g_xlo fp16.
// ---------------------------------------------------------------------------
__global__ void asplit_kernel(const float* __restrict__ src) {
    size_t i = (size_t)blockIdx.x * 256 + threadIdx.x;
    float4 v = ((const float4*)src)[i];
    ushort4 h, l;
    split1(v.x, h.x, l.x);
    split1(v.y, h.y, l.y);
    split1(v.z, h.z, l.z);
    split1(v.w, h.w, l.w);
    ((ushort4*)g_xhi)[i] = h;
    ((ushort4*)g_xlo)[i] = l;
}

// All 4 weights in one launch: W [K,N] fp32 -> g_bhi slot z, [N,K] fp16 hi.
__global__ void wsplit_kernel(const float* __restrict__ W0,
                              const float* __restrict__ W1,
                              const float* __restrict__ W2,
                              const float* __restrict__ W3) {
    __shared__ float ts[32][33];
    const int tx = threadIdx.x, ty = threadIdx.y;
    const int n0 = blockIdx.x * 32, k0 = blockIdx.y * 32;
    const int widx = blockIdx.z;
    const float* W = (widx == 0) ? W0 : (widx == 1) ? W1 : (widx == 2) ? W2 : W3;
    __half* bh = g_bhi + (size_t)widx * HID_ * HID_;
#pragma unroll
    for (int i = 0; i < 4; i++)
        ts[ty + 8 * i][tx] = W[(size_t)(k0 + ty + 8 * i) * HID_ + n0 + tx];
    __syncthreads();
#pragma unroll
    for (int i = 0; i < 4; i++) {
        int n = n0 + ty + 8 * i;
        int k = k0 + tx;
        bh[(size_t)n * HID_ + k] = __float2half_rn(ts[tx][ty + 8 * i]);
    }
}

// ---------------------------------------------------------------------------
// mma.sync fp16x2 GEMM. CTA tile 128x256, 512 threads, 16 warps (4m x 4n),
// warp tile 32x64 (proven register footprint: acc = 64 regs). 2-stage
// double buffer (147KB), 1 CTA/SM, 4 warps/SMSP. L2 demand per SM drops to
// ~18 B/cyc (was ~54 at 128x128 x2CTA — above the ~42 LTS share).
// MODE==1: fused QKV (blockIdx.x = widx*8 + nblk; 2 heads per n-tile).
// MODE==0: O projection.
// ---------------------------------------------------------------------------
#define PITCH 144
#define ASTG (128 * PITCH)            // 18432 per A matrix (hi or lo)
#define BSTG (256 * PITCH)            // 36864
#define STGB (2 * ASTG + BSTG)        // 73728 per stage
#define GEMM_SMEM (2 * STGB)          // 147456
#define NCH (HID_ / 64)               // 32

template <int MODE>
__global__ __launch_bounds__(512, 1) void mma_gemm(float* __restrict__ Cout) {
    extern __shared__ char dsm[];
    const uint32_t sb = smem_u32(dsm);
    const int t = threadIdx.x;
    const int lane = t & 31, wid = t >> 5;       // 16 warps
    const int wm = wid & 3, wn = wid >> 2;       // 4m x 4n
    const int m0 = blockIdx.y * 128;
    const int widx = (MODE == 1) ? (blockIdx.x >> 3) : 3;
    const int nblk = (MODE == 1) ? (blockIdx.x & 7) : blockIdx.x;
    const int n0 = nblk * 256;

    const __half* __restrict__ AH = g_xhi;
    const __half* __restrict__ AL = g_xlo;
    const __half* __restrict__ BH = g_bhi + (size_t)widx * HID_ * HID_;

    float acc[2][8][4];
#pragma unroll
    for (int i = 0; i < 2; i++)
#pragma unroll
        for (int j = 0; j < 8; j++)
#pragma unroll
            for (int k = 0; k < 4; k++) acc[i][j][k] = 0.f;

    const int lrow = t >> 3;          // 0..63
    const int lch = t & 7;

    // prologue: stage 0
    {
#pragma unroll
        for (int j = 0; j < 2; j++) {     // A rows 0..127 (hi + lo)
            int row = lrow + j * 64;
            uint32_t sa = sb + row * PITCH + lch * 16;
            size_t ga = (size_t)(m0 + row) * HID_ + lch * 8;
            cpa16(sa, AH + ga);
            cpa16(sa + ASTG, AL + ga);
        }
#pragma unroll
        for (int j = 0; j < 4; j++) {     // B rows 0..255
            int row = lrow + j * 64;
            uint32_t sa = sb + 2 * ASTG + row * PITCH + lch * 16;
            size_t gb = (size_t)(n0 + row) * HID_ + lch * 8;
            cpa16(sa, BH + gb);
        }
        CP_COMMIT();
    }

    const uint32_t lm_a_off =
        (uint32_t)((wm * 32 + (lane & 15)) * PITCH + (lane >> 4) * 16);
    const uint32_t lm_b_off =
        (uint32_t)((wn * 64 + (lane & 15)) * PITCH + (lane >> 4) * 16);

    for (int c = 0; c < NCH; c++) {
        CP_WAIT0();           // load for chunk c complete
        __syncthreads();      // all warps past reads of buffer we'll fill

        if (c + 1 < NCH) {
            const uint32_t base = sb + ((c + 1) & 1) * STGB;
            const int k0 = (c + 1) * 64;
#pragma unroll
            for (int j = 0; j < 2; j++) {
                int row = lrow + j * 64;
                uint32_t sa = base + row * PITCH + lch * 16;
                size_t ga = (size_t)(m0 + row) * HID_ + k0 + lch * 8;
                cpa16(sa, AH + ga);
                cpa16(sa + ASTG, AL + ga);
            }
#pragma unroll
            for (int j = 0; j < 4; j++) {
                int row = lrow + j * 64;
                uint32_t sa = base + 2 * ASTG + row * PITCH + lch * 16;
                size_t gb = (size_t)(n0 + row) * HID_ + k0 + lch * 8;
                cpa16(sa, BH + gb);
            }
            CP_COMMIT();
        }

        const uint32_t cb = sb + (c & 1) * STGB;
#pragma unroll
        for (int ks = 0; ks < 4; ks++) {
            uint32_t ah[2][4], al[2][4];
#pragma unroll
            for (int mt = 0; mt < 2; mt++) {
                uint32_t addr = cb + lm_a_off + mt * (16 * PITCH) + ks * 32;
                LDSM4(ah[mt], addr);
                LDSM4(al[mt], addr + ASTG);
            }
            uint32_t bh[8][2];
#pragma unroll
            for (int np = 0; np < 4; np++) {
                uint32_t addr = cb + 2 * ASTG + lm_b_off + np * (16 * PITCH) + ks * 32;
                uint32_t r[4];
                LDSM4(r, addr);
                bh[2 * np][0] = r[0]; bh[2 * np + 1][0] = r[1];
                bh[2 * np][1] = r[2]; bh[2 * np + 1][1] = r[3];
            }
#pragma unroll
            for (int mt = 0; mt < 2; mt++)
#pragma unroll
                for (int nt = 0; nt < 8; nt++)
                    MMAF32(acc[mt][nt], ah[mt], bh[nt]);
#pragma unroll
            for (int mt = 0; mt < 2; mt++)
#pragma unroll
                for (int nt = 0; nt < 8; nt++)
                    MMAF32(acc[mt][nt], al[mt], bh[nt]);
        }
    }

    // Epilogue: warp covers cols n0 + wn*64 .. +63
    const int qrow = lane >> 2;
    const int qcol = (lane & 3) * 2;
#pragma unroll
    for (int mt = 0; mt < 2; mt++) {
#pragma unroll
        for (int half_ = 0; half_ < 2; half_++) {
            const int m = m0 + wm * 32 + mt * 16 + qrow + half_ * 8;
            if (MODE == 1) {
                const int head = nblk * 2 + (wn >> 1);
                const int cbase = (wn & 1) * 64;
                int b_ = m >> 11, s_ = m & (S_ - 1);
                size_t base = (((size_t)b_ * H_ + head) * S_ + s_) * D_;
                if (widx == 2) {
#pragma unroll
                    for (int nt = 0; nt < 8; nt++) {
                        int col = cbase + nt * 8 + qcol;
                        *(uint32_t*)(g_vh + base + col) =
                            f2h2(acc[mt][nt][half_ * 2], acc[mt][nt][half_ * 2 + 1]);
                    }
                } else {
                    float* dst = (widx == 0) ? g_q : g_k;
#pragma unroll
                    for (int nt = 0; nt < 8; nt++) {
                        int col = cbase + nt * 8 + qcol;
                        *(float2*)(dst + base + col) =
                            make_float2(acc[mt][nt][half_ * 2], acc[mt][nt][half_ * 2 + 1]);
                    }
                }
            } else {
                size_t base = (size_t)m * HID_ + n0 + wn * 64;
#pragma unroll
                for (int nt = 0; nt < 8; nt++) {
                    int col = nt * 8 + qcol;
                    *(float2*)(Cout + base + col) =
                        make_float2(acc[mt][nt][half_ * 2], acc[mt][nt][half_ * 2 + 1]);
                }
            }
        }
    }
}

// ---------------------------------------------------------------------------
// RoPE: read fp32 g_q/g_k, rotate, emit qh/ql (fp16 split) and kh (round).
// ---------------------------------------------------------------------------
__global__ void rope_split_kernel(const float* __restrict__ cosb,
                                  const float* __restrict__ sinb) {
    int tid = blockIdx.x * 256 + threadIdx.x;
    int d = tid & 63;
    int s = (tid >> 6) & (S_ - 1);
    int bh = tid >> 17;
    size_t base = ((size_t)bh * S_ + s) * D_;
    float c0 = cosb[s * D_ + d], c1 = cosb[s * D_ + d + 64];
    float s0 = sinb[s * D_ + d], s1 = sinb[s * D_ + d + 64];

    float q0 = g_q[base + d], q1 = g_q[base + d + 64];
    float k0 = g_k[base + d], k1 = g_k[base + d + 64];
    float qa = q0 * c0 - q1 * s0;
    float qb = q1 * c1 + q0 * s1;
    float ka = k0 * c0 - k1 * s0;
    float kb = k1 * c1 + k0 * s1;

    unsigned short h, l;
    split1(qa, h, l);
    g_qh[base + d] = __ushort_as_half(h);
    g_ql[base + d] = __ushort_as_half(l);
    split1(qb, h, l);
    g_qh[base + d + 64] = __ushort_as_half(h);
    g_ql[base + d + 64] = __ushort_as_half(l);
    g_kh[base + d] = __float2half_rn(ka);
    g_kh[base + d + 64] = __float2half_rn(kb);
}

// ---------------------------------------------------------------------------
// Flash attention (unchanged from R13 — proven config).
// CTA = 64 q-rows, 128 threads, K/V 64-key tiles double-buffered, 2 CTAs/SM.
// ---------------------------------------------------------------------------
#define AP    272
#define AMAT2 (64 * AP)               // 17408
#define ATTN_SMEM (6 * AMAT2)         // 104448
#define KT_   64
#define NKT   (S_ / KT_)              // 32

__global__ __launch_bounds__(128, 2) void attn_mma_kernel() {
    extern __shared__ char sm8[];
    const uint32_t sb = smem_u32(sm8);
    const uint32_t Qh = sb, Ql = sb + AMAT2;

    const int t = threadIdx.x, lane = t & 31, wid = t >> 5;
    const int bh = blockIdx.y;
    const int q0 = blockIdx.x * 64;
    const size_t qoff = ((size_t)bh * S_ + q0) * D_;
    const size_t koff = (size_t)bh * S_ * D_;

    const int lrow = t >> 4;
    const int lch = t & 15;

    // prologue: Q(hi,lo) + K0 + V0 in ONE group
    {
        const uint32_t K0 = sb + 2 * AMAT2, V0 = sb + 4 * AMAT2;
#pragma unroll
        for (int j = 0; j < 8; j++) {
            int row = lrow + j * 8;
            uint32_t so = (uint32_t)(row * AP + lch * 16);
            size_t gq = qoff + (size_t)row * D_ + lch * 8;
            size_t gk = koff + (size_t)row * D_ + lch * 8;
            cpa16(Qh + so, g_qh + gq);
            cpa16(Ql + so, g_ql + gq);
            cpa16(K0 + so, g_kh + gk);
            cpa16(V0 + so, g_vh + gk);
        }
        CP_COMMIT();
    }

    float sa[8][4];
    float oa[16][4];
#pragma unroll
    for (int i = 0; i < 16; i++)
#pragma unroll
        for (int j = 0; j < 4; j++) oa[i][j] = 0.f;
    float m0r = -1e30f, m1r = -1e30f, l0r = 0.f, l1r = 0.f;

    const float scale = 0.088388347648318447f;
    const uint32_t a_off =
        (uint32_t)((wid * 16 + (lane & 15)) * AP + (lane >> 4) * 16);
    const uint32_t lm_lo = (uint32_t)((lane & 15) * AP + (lane >> 4) * 16);

    for (int kt = 0; kt < NKT; kt++) {
        CP_WAIT0();
        __syncthreads();

        if (kt + 1 < NKT) {
            const uint32_t Kn = sb + (2 + ((kt + 1) & 1)) * AMAT2;
            const uint32_t Vn = sb + (4 + ((kt + 1) & 1)) * AMAT2;
#pragma unroll
            for (int j = 0; j < 8; j++) {
                int row = lrow + j * 8;
                uint32_t so = (uint32_t)(row * AP + lch * 16);
                size_t gk = koff + (size_t)((kt + 1) * KT_ + row) * D_ + lch * 8;
                cpa16(Kn + so, g_kh + gk);
                cpa16(Vn + so, g_vh + gk);
            }
        }
        CP_COMMIT();

        const uint32_t Kc = sb + (2 + (kt & 1)) * AMAT2;
        const uint32_t Vc = sb + (4 + (kt & 1)) * AMAT2;

#pragma unroll
        for (int i = 0; i < 8; i++)
#pragma unroll
            for (int j = 0; j < 4; j++) sa[i][j] = 0.f;

        // ---- S = Q K^T (64 keys) ----
#pragma unroll
        for (int ks = 0; ks < 8; ks++) {
            uint32_t qh[4], ql[4];
            LDSM4(qh, Qh + a_off + ks * 32);
            LDSM4(ql, Ql + a_off + ks * 32);
            uint32_t kA[4][2], kB[4][2];
#pragma unroll
            for (int np = 0; np < 4; np++) {
                uint32_t r[4];
                LDSM4(r, Kc + lm_lo + (uint32_t)(np * 16 * AP) + ks * 32);
                kA[np][0] = r[0]; kB[np][0] = r[1];
                kA[np][1] = r[2]; kB[np][1] = r[3];
            }
#pragma unroll
            for (int np = 0; np < 4; np++) {
                MMAF32(sa[2 * np], qh, kA[np]);
                MMAF32(sa[2 * np + 1], qh, kB[np]);
            }
#pragma unroll
            for (int np = 0; np < 4; np++) {
                MMAF32(sa[2 * np], ql, kA[np]);
                MMAF32(sa[2 * np + 1], ql, kB[np]);
            }
        }

        // ---- online softmax ----
        float rm0 = -1e30f, rm1 = -1e30f;
#pragma unroll
        for (int nt = 0; nt < 8; nt++) {
            rm0 = fmaxf(rm0, fmaxf(sa[nt][0], sa[nt][1]));
            rm1 = fmaxf(rm1, fmaxf(sa[nt][2], sa[nt][3]));
        }
#pragma unroll
        for (int off = 1; off <= 2; off <<= 1) {
            rm0 = fmaxf(rm0, __shfl_xor_sync(0xffffffffu, rm0, off));
            rm1 = fmaxf(rm1, __shfl_xor_sync(0xffffffffu, rm1, off));
        }
        float mn0 = fmaxf(m0r, rm0 * scale);
        float mn1 = fmaxf(m1r, rm1 * scale);
        float al0 = __expf(m0r - mn0);
        float al1 = __expf(m1r - mn1);
        m0r = mn0;
        m1r = mn1;
        float rs0 = 0.f, rs1 = 0.f;
#pragma unroll
        for (int nt = 0; nt < 8; nt++) {
            float p0 = __expf(fmaf(sa[nt][0], scale, -mn0));
            float p1 = __expf(fmaf(sa[nt][1], scale, -mn0));
            float p2 = __expf(fmaf(sa[nt][2], scale, -mn1));
            float p3 = __expf(fmaf(sa[nt][3], scale, -mn1));
            sa[nt][0] = p0; sa[nt][1] = p1; sa[nt][2] = p2; sa[nt][3] = p3;
            rs0 += p0 + p1;
            rs1 += p2 + p3;
        }
#pragma unroll
        for (int off = 1; off <= 2; off <<= 1) {
            rs0 += __shfl_xor_sync(0xffffffffu, rs0, off);
            rs1 += __shfl_xor_sync(0xffffffffu, rs1, off);
        }
        l0r = l0r * al0 + rs0;
        l1r = l1r * al1 + rs1;
#pragma unroll
        for (int nt = 0; nt < 16; nt++) {
            oa[nt][0] *= al0;
            oa[nt][1] *= al0;
            oa[nt][2] *= al1;
            oa[nt][3] *= al1;
        }

        // ---- O += P V ----
#pragma unroll
        for (int ks = 0; ks < 4; ks++) {
            uint32_t aH[4], aL[4];
#pragma unroll
            for (int g = 0; g < 2; g++) {
                const int tt = 2 * ks + g;
                float x0 = sa[tt][0], y0 = sa[tt][1];
                float x1 = sa[tt][2], y1 = sa[tt][3];
                uint32_t h0 = f2h2(x0, y0);
                uint32_t h1 = f2h2(x1, y1);
                float2 b0 = h2f2(h0);
                float2 b1 = h2f2(h1);
                aH[2 * g]     = h0;
                aH[2 * g + 1] = h1;
                aL[2 * g]     = f2h2(x0 - b0.x, y0 - b0.y);
                aL[2 * g + 1] = f2h2(x1 - b1.x, y1 - b1.y);
            }
            const uint32_t vbase = lm_lo + (uint32_t)(ks * 16 * AP);
#pragma unroll
            for (int h2 = 0; h2 < 2; h2++) {
                uint32_t vA[4][2], vB[4][2];
#pragma unroll
                for (int j = 0; j < 4; j++) {
                    const int np = h2 * 4 + j;
                    uint32_t r[4];
                    LDSM4T(r, Vc + vbase + np * 32);
                    vA[j][0] = r[0]; vA[j][1] = r[1];
                    vB[j][0] = r[2]; vB[j][1] = r[3];
                }
#pragma unroll
                for (int j = 0; j < 4; j++) {
                    const int np = h2 * 4 + j;
                    MMAF32(oa[2 * np], aH, vA[j]);
                    MMAF32(oa[2 * np + 1], aH, vB[j]);
                }
#pragma unroll
                for (int j = 0; j < 4; j++) {
                    const int np = h2 * 4 + j;
                    MMAF32(oa[2 * np], aL, vA[j]);
                    MMAF32(oa[2 * np + 1], aL, vB[j]);
                }
            }
        }
    }

    // ---- finalize: write xhi/xlo fp16 splits of attn output directly ----
    const int b_ = bh >> 4, h = bh & 15;
    const int row0 = q0 + wid * 16 + (lane >> 2);
    const float inv0 = 1.0f / l0r, inv1 = 1.0f / l1r;
    const size_t base0 = ((size_t)b_ * S_ + row0) * HID_ + h * D_;
    const size_t base1 = ((size_t)b_ * S_ + row0 + 8) * HID_ + h * D_;
    const int col0 = (lane & 3) * 2;
#pragma unroll
    for (int nt = 0; nt < 16; nt++) {
        int col = 8 * nt + col0;
        float x0 = oa[nt][0] * inv0, y0 = oa[nt][1] * inv0;
        float x1 = oa[nt][2] * inv1, y1 = oa[nt][3] * inv1;
        unsigned short hx, lx, hy, ly;
        split1(x0, hx, lx);
        split1(y0, hy, ly);
        *(uint32_t*)(g_xhi + base0 + col) = (uint32_t)hx | ((uint32_t)hy << 16);
        *(uint32_t*)(g_xlo + base0 + col) = (uint32_t)lx | ((uint32_t)ly << 16);
        split1(x1, hx, lx);
        split1(y1, hy, ly);
        *(uint32_t*)(g_xhi + base1 + col) = (uint32_t)hx | ((uint32_t)hy << 16);
        *(uint32_t*)(g_xlo + base1 + col) = (uint32_t)lx | ((uint32_t)ly << 16);
    }
}

// ---------------------------------------------------------------------------
// Launch
// ---------------------------------------------------------------------------
extern "C" void kernel_launch(void* const* d_in, const int* in_sizes, int n_in,
                              void* d_out, int out_size) {
    const float* X = (const float*)d_in[0];
    const float* cosb = (const float*)d_in[1];
    const float* sinb = (const float*)d_in[2];
    const float* Wq = (const float*)d_in[3];
    const float* Wk = (const float*)d_in[4];
    const float* Wv = (const float*)d_in[5];
    const float* Wo = (const float*)d_in[6];
    float* out = (float*)d_out;

    cudaFuncSetAttribute(mma_gemm<0>, cudaFuncAttributeMaxDynamicSharedMemorySize, GEMM_SMEM);
    cudaFuncSetAttribute(mma_gemm<1>, cudaFuncAttributeMaxDynamicSharedMemorySize, GEMM_SMEM);
    cudaFuncSetAttribute(attn_mma_kernel, cudaFuncAttributeMaxDynamicSharedMemorySize, ATTN_SMEM);

    // all weight conversions in one launch; activations split
    wsplit_kernel<<<dim3(64, 64, 4), dim3(32, 8)>>>(Wq, Wk, Wv, Wo);
    asplit_kernel<<<(M_ * HID_ / 4) / 256, 256>>>(X);

    // fused QKV projection: 3 weights x 8 n-tiles (256-wide), 32 m-tiles
    mma_gemm<1><<<dim3(24, M_ / 128), 512, GEMM_SMEM>>>(nullptr);

    rope_split_kernel<<<(B_ * H_ * S_ * 64) / 256, 256>>>(cosb, sinb);

    // attention: 64 q-rows per CTA, 128 threads, 2 CTAs/SM
    attn_mma_kernel<<<dim3(S_ / 64, B_ * H_), 128, ATTN_SMEM>>>();

    // O projection: 8 n-tiles x 32 m-tiles
    mma_gemm<0><<<dim3(HID_ / 256, M_ / 128), 512, GEMM_SMEM>>>(out);
}

// round 16
// speedup vs baseline: 1.0588x; 1.0413x over previous
#include <cuda_runtime.h>
#include <cuda_fp16.h>
#include <cstdint>

// ---------------------------------------------------------------------------
// Problem constants
// ---------------------------------------------------------------------------
#define B_ 2
#define S_ 2048
#define H_ 16
#define D_ 128
#define HID_ 2048
#define M_ (B_ * S_)   // 4096

// Scratch (device globals — allocation-free per harness rules)
__device__ float g_q[(size_t)B_ * H_ * S_ * D_];   // fp32 Q pre-rope [b,h,s,d]
__device__ float g_k[(size_t)B_ * H_ * S_ * D_];   // fp32 K pre-rope

// fp16 buffers. Activations split hi/lo; weights hi only (2-term emulation).
__device__ __half g_xhi[(size_t)M_ * HID_];
__device__ __half g_xlo[(size_t)M_ * HID_];
__device__ __half g_bhi[(size_t)4 * HID_ * HID_];

// fp16 attention operands [b,h,s,d]: Q split hi/lo; K, V hi only.
#define QKV_ELEMS ((size_t)B_ * H_ * S_ * D_)
__device__ __half g_qh[QKV_ELEMS];
__device__ __half g_ql[QKV_ELEMS];
__device__ __half g_kh[QKV_ELEMS];
__device__ __half g_vh[QKV_ELEMS];

// ---------------------------------------------------------------------------
// PTX helpers (non-'a' features only)
// ---------------------------------------------------------------------------
__device__ __forceinline__ uint32_t smem_u32(const void* p) {
    uint32_t a;
    asm("{ .reg .u64 t; cvta.to.shared.u64 t, %1; cvt.u32.u64 %0, t; }"
        : "=r"(a) : "l"(p));
    return a;
}
__device__ __forceinline__ void cpa16(uint32_t s, const void* g) {
    asm volatile("cp.async.cg.shared.global [%0], [%1], 16;" :: "r"(s), "l"(g));
}
#define CP_COMMIT() asm volatile("cp.async.commit_group;" ::: "memory")
#define CP_WAIT0()  asm volatile("cp.async.wait_group 0;" ::: "memory")
#define CP_WAIT1()  asm volatile("cp.async.wait_group 1;" ::: "memory")

#define LDSM4(r, addr)                                                        \
    asm volatile("ldmatrix.sync.aligned.m8n8.x4.shared.b16 {%0,%1,%2,%3}, [%4];" \
                 : "=r"((r)[0]), "=r"((r)[1]), "=r"((r)[2]), "=r"((r)[3])     \
                 : "r"(addr))
#define LDSM4T(r, addr)                                                       \
    asm volatile("ldmatrix.sync.aligned.m8n8.x4.trans.shared.b16 {%0,%1,%2,%3}, [%4];" \
                 : "=r"((r)[0]), "=r"((r)[1]), "=r"((r)[2]), "=r"((r)[3])     \
                 : "r"(addr))

#define MMAF32(d, a, b)                                                       \
    asm volatile(                                                             \
        "mma.sync.aligned.m16n8k16.row.col.f32.f16.f16.f32 "                  \
        "{%0,%1,%2,%3}, {%4,%5,%6,%7}, {%8,%9}, {%0,%1,%2,%3};"               \
        : "+f"((d)[0]), "+f"((d)[1]), "+f"((d)[2]), "+f"((d)[3])              \
        : "r"((a)[0]), "r"((a)[1]), "r"((a)[2]), "r"((a)[3]),                 \
          "r"((b)[0]), "r"((b)[1]))

__device__ __forceinline__ float2 h2f2(uint32_t u) {
    __half2 h = *(__half2*)&u;
    return __half22float2(h);
}
__device__ __forceinline__ uint32_t f2h2(float x, float y) {
    __half2 h = __float22half2_rn(make_float2(x, y));
    return *(uint32_t*)&h;
}

// fp32 -> fp16 hi/lo split
__device__ __forceinline__ void split1(float x, unsigned short& h, unsigned short& l) {
    __half hb = __float2half_rn(x);
    __half lb = __float2half_rn(x - __half2float(hb));
    h = __half_as_ushort(hb);
    l = __half_as_ushort(lb);
}

// ---------------------------------------------------------------------------
// Activations: X [M,K] fp32 -> g_xhi/g_xlo fp16.
// ---------------------------------------------------------------------------
__global__ void asplit_kernel(const float* __restrict__ src) {
    size_t i = (size_t)blockIdx.x * 256 + threadIdx.x;
    float4 v = ((const float4*)src)[i];
    ushort4 h, l;
    split1(v.x, h.x, l.x);
    split1(v.y, h.y, l.y);
    split1(v.z, h.z, l.z);
    split1(v.w, h.w, l.w);
    ((ushort4*)g_xhi)[i] = h;
    ((ushort4*)g_xlo)[i] = l;
}

// All 4 weights in one launch: W [K,N] fp32 -> g_bhi slot z, [N,K] fp16 hi.
__global__ void wsplit_kernel(const float* __restrict__ W0,
                              const float* __restrict__ W1,
                              const float* __restrict__ W2,
                              const float* __restrict__ W3) {
    __shared__ float ts[32][33];
    const int tx = threadIdx.x, ty = threadIdx.y;
    const int n0 = blockIdx.x * 32, k0 = blockIdx.y * 32;
    const int widx = blockIdx.z;
    const float* W = (widx == 0) ? W0 : (widx == 1) ? W1 : (widx == 2) ? W2 : W3;
    __half* bh = g_bhi + (size_t)widx * HID_ * HID_;
#pragma unroll
    for (int i = 0; i < 4; i++)
        ts[ty + 8 * i][tx] = W[(size_t)(k0 + ty + 8 * i) * HID_ + n0 + tx];
    __syncthreads();
#pragma unroll
    for (int i = 0; i < 4; i++) {
        int n = n0 + ty + 8 * i;
        int k = k0 + tx;
        bh[(size_t)n * HID_ + k] = __float2half_rn(ts[tx][ty + 8 * i]);
    }
}

// ---------------------------------------------------------------------------
// mma.sync fp16x2 GEMM (R13 config: 128x128, 256 threads, 2-stage, 2 CTA/SM)
// MODE==1: fused QKV (blockIdx.x = widx*16 + head). MODE==0: O projection.
// ---------------------------------------------------------------------------
#define PITCH 144
#define MATB  (128 * PITCH)          // 18432
#define BUFB  (3 * MATB)             // 55296 (Ah, Al, Bh)
#define GEMM_SMEM (2 * BUFB)         // 110592 -> two CTAs fit per SM
#define NCH (HID_ / 64)              // 32

template <int MODE>
__global__ __launch_bounds__(256, 2) void mma_gemm(float* __restrict__ Cout) {
    extern __shared__ char dsm[];
    const uint32_t sb = smem_u32(dsm);
    const int t = threadIdx.x;
    const int lane = t & 31, wid = t >> 5;
    const int wm = wid & 3, wn = wid >> 2;
    const int m0 = blockIdx.y * 128;
    const int widx = (MODE == 1) ? (blockIdx.x >> 4) : 3;
    const int nblk = (MODE == 1) ? (blockIdx.x & 15) : blockIdx.x;
    const int n0 = nblk * 128;

    const __half* __restrict__ AH = g_xhi;
    const __half* __restrict__ AL = g_xlo;
    const __half* __restrict__ BH = g_bhi + (size_t)widx * HID_ * HID_;

    float acc[2][8][4];
#pragma unroll
    for (int i = 0; i < 2; i++)
#pragma unroll
        for (int j = 0; j < 8; j++)
#pragma unroll
            for (int k = 0; k < 4; k++) acc[i][j][k] = 0.f;

    const int lrow = t >> 3;
    const int lch = t & 7;

    {
#pragma unroll
        for (int j = 0; j < 4; j++) {
            int row = lrow + j * 32;
            uint32_t sa = sb + row * PITCH + lch * 16;
            size_t ga = (size_t)(m0 + row) * HID_ + lch * 8;
            size_t gb = (size_t)(n0 + row) * HID_ + lch * 8;
            cpa16(sa, AH + ga);
            cpa16(sa + MATB, AL + ga);
            cpa16(sa + 2 * MATB, BH + gb);
        }
        CP_COMMIT();
    }

    const uint32_t lm_a_off =
        (uint32_t)((wm * 32 + (lane & 15)) * PITCH + (lane >> 4) * 16);
    const uint32_t lm_b_off =
        (uint32_t)((wn * 64 + (lane & 15)) * PITCH + (lane >> 4) * 16);

    for (int c = 0; c < NCH; c++) {
        CP_WAIT0();
        __syncthreads();

        if (c + 1 < NCH) {
            const uint32_t base = sb + ((c + 1) & 1) * BUFB;
            const int k0 = (c + 1) * 64;
#pragma unroll
            for (int j = 0; j < 4; j++) {
                int row = lrow + j * 32;
                uint32_t sa = base + row * PITCH + lch * 16;
                size_t ga = (size_t)(m0 + row) * HID_ + k0 + lch * 8;
                size_t gb = (size_t)(n0 + row) * HID_ + k0 + lch * 8;
                cpa16(sa, AH + ga);
                cpa16(sa + MATB, AL + ga);
                cpa16(sa + 2 * MATB, BH + gb);
            }
            CP_COMMIT();
        }

        const uint32_t cb = sb + (c & 1) * BUFB;
#pragma unroll
        for (int ks = 0; ks < 4; ks++) {
            uint32_t ah[2][4], al[2][4];
#pragma unroll
            for (int mt = 0; mt < 2; mt++) {
                uint32_t addr = cb + lm_a_off + mt * (16 * PITCH) + ks * 32;
                LDSM4(ah[mt], addr);
                LDSM4(al[mt], addr + MATB);
            }
            uint32_t bh[8][2];
#pragma unroll
            for (int np = 0; np < 4; np++) {
                uint32_t addr = cb + 2 * MATB + lm_b_off + np * (16 * PITCH) + ks * 32;
                uint32_t r[4];
                LDSM4(r, addr);
                bh[2 * np][0] = r[0]; bh[2 * np + 1][0] = r[1];
                bh[2 * np][1] = r[2]; bh[2 * np + 1][1] = r[3];
            }
#pragma unroll
            for (int mt = 0; mt < 2; mt++)
#pragma unroll
                for (int nt = 0; nt < 8; nt++)
                    MMAF32(acc[mt][nt], ah[mt], bh[nt]);
#pragma unroll
            for (int mt = 0; mt < 2; mt++)
#pragma unroll
                for (int nt = 0; nt < 8; nt++)
                    MMAF32(acc[mt][nt], al[mt], bh[nt]);
        }
    }

    const int qrow = lane >> 2;
    const int qcol = (lane & 3) * 2;
#pragma unroll
    for (int mt = 0; mt < 2; mt++) {
#pragma unroll
        for (int half_ = 0; half_ < 2; half_++) {
            const int m = m0 + wm * 32 + mt * 16 + qrow + half_ * 8;
            if (MODE == 1 && widx == 2) {
                int b_ = m >> 11, s_ = m & (S_ - 1);
                size_t base = (((size_t)b_ * H_ + nblk) * S_ + s_) * D_;
#pragma unroll
                for (int nt = 0; nt < 8; nt++) {
                    int col = wn * 64 + nt * 8 + qcol;
                    *(uint32_t*)(g_vh + base + col) =
                        f2h2(acc[mt][nt][half_ * 2], acc[mt][nt][half_ * 2 + 1]);
                }
            } else {
                float* dst;
                size_t base;
                if (MODE == 0) {
                    dst = Cout;
                    base = (size_t)m * HID_ + n0;
                } else {
                    int b_ = m >> 11, s_ = m & (S_ - 1);
                    dst = (widx == 0) ? g_q : g_k;
                    base = (((size_t)b_ * H_ + nblk) * S_ + s_) * D_;
                }
#pragma unroll
                for (int nt = 0; nt < 8; nt++) {
                    int col = wn * 64 + nt * 8 + qcol;
                    *(float2*)(dst + base + col) =
                        make_float2(acc[mt][nt][half_ * 2], acc[mt][nt][half_ * 2 + 1]);
                }
            }
        }
    }
}

// ---------------------------------------------------------------------------
// RoPE (vectorized): thread handles 4 consecutive d in [0,64); float4 loads,
// packed 8-byte fp16 stores. Per-element arithmetic identical to scalar ver.
// ---------------------------------------------------------------------------
__global__ void rope_split_kernel(const float* __restrict__ cosb,
                                  const float* __restrict__ sinb) {
    int tid = blockIdx.x * 256 + threadIdx.x;      // B_*H_*S_*16 threads
    int d = (tid & 15) * 4;                        // 0..60
    int s = (tid >> 4) & (S_ - 1);
    int bh = tid >> 15;
    size_t base = ((size_t)bh * S_ + s) * D_;

    float4 c0 = *(const float4*)(cosb + s * D_ + d);
    float4 c1 = *(const float4*)(cosb + s * D_ + d + 64);
    float4 s0 = *(const float4*)(sinb + s * D_ + d);
    float4 s1 = *(const float4*)(sinb + s * D_ + d + 64);
    float4 q0 = *(const float4*)(g_q + base + d);
    float4 q1 = *(const float4*)(g_q + base + d + 64);
    float4 k0 = *(const float4*)(g_k + base + d);
    float4 k1 = *(const float4*)(g_k + base + d + 64);

    float qa[4], qb[4], ka[4], kb[4];
    {
        const float* q0p = &q0.x; const float* q1p = &q1.x;
        const float* k0p = &k0.x; const float* k1p = &k1.x;
        const float* c0p = &c0.x; const float* c1p = &c1.x;
        const float* s0p = &s0.x; const float* s1p = &s1.x;
#pragma unroll
        for (int e = 0; e < 4; e++) {
            qa[e] = q0p[e] * c0p[e] - q1p[e] * s0p[e];
            qb[e] = q1p[e] * c1p[e] + q0p[e] * s1p[e];
            ka[e] = k0p[e] * c0p[e] - k1p[e] * s0p[e];
            kb[e] = k1p[e] * c1p[e] + k0p[e] * s1p[e];
        }
    }

    unsigned short h[4], l[4];
#pragma unroll
    for (int e = 0; e < 4; e++) split1(qa[e], h[e], l[e]);
    *(uint2*)(g_qh + base + d) = make_uint2(
        (uint32_t)h[0] | ((uint32_t)h[1] << 16), (uint32_t)h[2] | ((uint32_t)h[3] << 16));
    *(uint2*)(g_ql + base + d) = make_uint2(
        (uint32_t)l[0] | ((uint32_t)l[1] << 16), (uint32_t)l[2] | ((uint32_t)l[3] << 16));
#pragma unroll
    for (int e = 0; e < 4; e++) split1(qb[e], h[e], l[e]);
    *(uint2*)(g_qh + base + d + 64) = make_uint2(
        (uint32_t)h[0] | ((uint32_t)h[1] << 16), (uint32_t)h[2] | ((uint32_t)h[3] << 16));
    *(uint2*)(g_ql + base + d + 64) = make_uint2(
        (uint32_t)l[0] | ((uint32_t)l[1] << 16), (uint32_t)l[2] | ((uint32_t)l[3] << 16));

    *(uint2*)(g_kh + base + d) = make_uint2(
        f2h2(ka[0], ka[1]), f2h2(ka[2], ka[3]));
    *(uint2*)(g_kh + base + d + 64) = make_uint2(
        f2h2(kb[0], kb[1]), f2h2(kb[2], kb[3]));
}

// ---------------------------------------------------------------------------
// Flash attention (R13 config — proven best).
// CTA = 64 q-rows, 128 threads, K/V 64-key tiles double-buffered, 2 CTAs/SM.
// ---------------------------------------------------------------------------
#define AP    272
#define AMAT2 (64 * AP)               // 17408
#define ATTN_SMEM (6 * AMAT2)         // 104448
#define KT_   64
#define NKT   (S_ / KT_)              // 32

__global__ __launch_bounds__(128, 2) void attn_mma_kernel() {
    extern __shared__ char sm8[];
    const uint32_t sb = smem_u32(sm8);
    const uint32_t Qh = sb, Ql = sb + AMAT2;

    const int t = threadIdx.x, lane = t & 31, wid = t >> 5;
    const int bh = blockIdx.y;
    const int q0 = blockIdx.x * 64;
    const size_t qoff = ((size_t)bh * S_ + q0) * D_;
    const size_t koff = (size_t)bh * S_ * D_;

    const int lrow = t >> 4;
    const int lch = t & 15;

    // prologue: Q(hi,lo) + K0 + V0 in ONE group
    {
        const uint32_t K0 = sb + 2 * AMAT2, V0 = sb + 4 * AMAT2;
#pragma unroll
        for (int j = 0; j < 8; j++) {
            int row = lrow + j * 8;
            uint32_t so = (uint32_t)(row * AP + lch * 16);
            size_t gq = qoff + (size_t)row * D_ + lch * 8;
            size_t gk = koff + (size_t)row * D_ + lch * 8;
            cpa16(Qh + so, g_qh + gq);
            cpa16(Ql + so, g_ql + gq);
            cpa16(K0 + so, g_kh + gk);
            cpa16(V0 + so, g_vh + gk);
        }
        CP_COMMIT();
    }

    float sa[8][4];
    float oa[16][4];
#pragma unroll
    for (int i = 0; i < 16; i++)
#pragma unroll
        for (int j = 0; j < 4; j++) oa[i][j] = 0.f;
    float m0r = -1e30f, m1r = -1e30f, l0r = 0.f, l1r = 0.f;

    const float scale = 0.088388347648318447f;
    const uint32_t a_off =
        (uint32_t)((wid * 16 + (lane & 15)) * AP + (lane >> 4) * 16);
    const uint32_t lm_lo = (uint32_t)((lane & 15) * AP + (lane >> 4) * 16);

    for (int kt = 0; kt < NKT; kt++) {
        CP_WAIT0();
        __syncthreads();

        if (kt + 1 < NKT) {
            const uint32_t Kn = sb + (2 + ((kt + 1) & 1)) * AMAT2;
            const uint32_t Vn = sb + (4 + ((kt + 1) & 1)) * AMAT2;
#pragma unroll
            for (int j = 0; j < 8; j++) {
                int row = lrow + j * 8;
                uint32_t so = (uint32_t)(row * AP + lch * 16);
                size_t gk = koff + (size_t)((kt + 1) * KT_ + row) * D_ + lch * 8;
                cpa16(Kn + so, g_kh + gk);
                cpa16(Vn + so, g_vh + gk);
            }
        }
        CP_COMMIT();

        const uint32_t Kc = sb + (2 + (kt & 1)) * AMAT2;
        const uint32_t Vc = sb + (4 + (kt & 1)) * AMAT2;

#pragma unroll
        for (int i = 0; i < 8; i++)
#pragma unroll
            for (int j = 0; j < 4; j++) sa[i][j] = 0.f;

        // ---- S = Q K^T (64 keys) ----
#pragma unroll
        for (int ks = 0; ks < 8; ks++) {
            uint32_t qh[4], ql[4];
            LDSM4(qh, Qh + a_off + ks * 32);
            LDSM4(ql, Ql + a_off + ks * 32);
            uint32_t kA[4][2], kB[4][2];
#pragma unroll
            for (int np = 0; np < 4; np++) {
                uint32_t r[4];
                LDSM4(r, Kc + lm_lo + (uint32_t)(np * 16 * AP) + ks * 32);
                kA[np][0] = r[0]; kB[np][0] = r[1];
                kA[np][1] = r[2]; kB[np][1] = r[3];
            }
#pragma unroll
            for (int np = 0; np < 4; np++) {
                MMAF32(sa[2 * np], qh, kA[np]);
                MMAF32(sa[2 * np + 1], qh, kB[np]);
            }
#pragma unroll
            for (int np = 0; np < 4; np++) {
                MMAF32(sa[2 * np], ql, kA[np]);
                MMAF32(sa[2 * np + 1], ql, kB[np]);
            }
        }

        // ---- online softmax ----
        float rm0 = -1e30f, rm1 = -1e30f;
#pragma unroll
        for (int nt = 0; nt < 8; nt++) {
            rm0 = fmaxf(rm0, fmaxf(sa[nt][0], sa[nt][1]));
            rm1 = fmaxf(rm1, fmaxf(sa[nt][2], sa[nt][3]));
        }
#pragma unroll
        for (int off = 1; off <= 2; off <<= 1) {
            rm0 = fmaxf(rm0, __shfl_xor_sync(0xffffffffu, rm0, off));
            rm1 = fmaxf(rm1, __shfl_xor_sync(0xffffffffu, rm1, off));
        }
        float mn0 = fmaxf(m0r, rm0 * scale);
        float mn1 = fmaxf(m1r, rm1 * scale);
        float al0 = __expf(m0r - mn0);
        float al1 = __expf(m1r - mn1);
        m0r = mn0;
        m1r = mn1;
        float rs0 = 0.f, rs1 = 0.f;
#pragma unroll
        for (int nt = 0; nt < 8; nt++) {
            float p0 = __expf(fmaf(sa[nt][0], scale, -mn0));
            float p1 = __expf(fmaf(sa[nt][1], scale, -mn0));
            float p2 = __expf(fmaf(sa[nt][2], scale, -mn1));
            float p3 = __expf(fmaf(sa[nt][3], scale, -mn1));
            sa[nt][0] = p0; sa[nt][1] = p1; sa[nt][2] = p2; sa[nt][3] = p3;
            rs0 += p0 + p1;
            rs1 += p2 + p3;
        }
#pragma unroll
        for (int off = 1; off <= 2; off <<= 1) {
            rs0 += __shfl_xor_sync(0xffffffffu, rs0, off);
            rs1 += __shfl_xor_sync(0xffffffffu, rs1, off);
        }
        l0r = l0r * al0 + rs0;
        l1r = l1r * al1 + rs1;
#pragma unroll
        for (int nt = 0; nt < 16; nt++) {
            oa[nt][0] *= al0;
            oa[nt][1] *= al0;
            oa[nt][2] *= al1;
            oa[nt][3] *= al1;
        }

        // ---- O += P V ----
#pragma unroll
        for (int ks = 0; ks < 4; ks++) {
            uint32_t aH[4], aL[4];
#pragma unroll
            for (int g = 0; g < 2; g++) {
                const int tt = 2 * ks + g;
                float x0 = sa[tt][0], y0 = sa[tt][1];
                float x1 = sa[tt][2], y1 = sa[tt][3];
                uint32_t h0 = f2h2(x0, y0);
                uint32_t h1 = f2h2(x1, y1);
                float2 b0 = h2f2(h0);
                float2 b1 = h2f2(h1);
                aH[2 * g]     = h0;
                aH[2 * g + 1] = h1;
                aL[2 * g]     = f2h2(x0 - b0.x, y0 - b0.y);
                aL[2 * g + 1] = f2h2(x1 - b1.x, y1 - b1.y);
            }
            const uint32_t vbase = lm_lo + (uint32_t)(ks * 16 * AP);
#pragma unroll
            for (int h2 = 0; h2 < 2; h2++) {
                uint32_t vA[4][2], vB[4][2];
#pragma unroll
                for (int j = 0; j < 4; j++) {
                    const int np = h2 * 4 + j;
                    uint32_t r[4];
                    LDSM4T(r, Vc + vbase + np * 32);
                    vA[j][0] = r[0]; vA[j][1] = r[1];
                    vB[j][0] = r[2]; vB[j][1] = r[3];
                }
#pragma unroll
                for (int j = 0; j < 4; j++) {
                    const int np = h2 * 4 + j;
                    MMAF32(oa[2 * np], aH, vA[j]);
                    MMAF32(oa[2 * np + 1], aH, vB[j]);
                }
#pragma unroll
                for (int j = 0; j < 4; j++) {
                    const int np = h2 * 4 + j;
                    MMAF32(oa[2 * np], aL, vA[j]);
                    MMAF32(oa[2 * np + 1], aL, vB[j]);
                }
            }
        }
    }

    // ---- finalize: write xhi/xlo fp16 splits of attn output directly ----
    const int b_ = bh >> 4, h = bh & 15;
    const int row0 = q0 + wid * 16 + (lane >> 2);
    const float inv0 = 1.0f / l0r, inv1 = 1.0f / l1r;
    const size_t base0 = ((size_t)b_ * S_ + row0) * HID_ + h * D_;
    const size_t base1 = ((size_t)b_ * S_ + row0 + 8) * HID_ + h * D_;
    const int col0 = (lane & 3) * 2;
#pragma unroll
    for (int nt = 0; nt < 16; nt++) {
        int col = 8 * nt + col0;
        float x0 = oa[nt][0] * inv0, y0 = oa[nt][1] * inv0;
        float x1 = oa[nt][2] * inv1, y1 = oa[nt][3] * inv1;
        unsigned short hx, lx, hy, ly;
        split1(x0, hx, lx);
        split1(y0, hy, ly);
        *(uint32_t*)(g_xhi + base0 + col) = (uint32_t)hx | ((uint32_t)hy << 16);
        *(uint32_t*)(g_xlo + base0 + col) = (uint32_t)lx | ((uint32_t)ly << 16);
        split1(x1, hx, lx);
        split1(y1, hy, ly);
        *(uint32_t*)(g_xhi + base1 + col) = (uint32_t)hx | ((uint32_t)hy << 16);
        *(uint32_t*)(g_xlo + base1 + col) = (uint32_t)lx | ((uint32_t)ly << 16);
    }
}

// ---------------------------------------------------------------------------
// Launch
// ---------------------------------------------------------------------------
extern "C" void kernel_launch(void* const* d_in, const int* in_sizes, int n_in,
                              void* d_out, int out_size) {
    const float* X = (const float*)d_in[0];
    const float* cosb = (const float*)d_in[1];
    const float* sinb = (const float*)d_in[2];
    const float* Wq = (const float*)d_in[3];
    const float* Wk = (const float*)d_in[4];
    const float* Wv = (const float*)d_in[5];
    const float* Wo = (const float*)d_in[6];
    float* out = (float*)d_out;

    cudaFuncSetAttribute(mma_gemm<0>, cudaFuncAttributeMaxDynamicSharedMemorySize, GEMM_SMEM);
    cudaFuncSetAttribute(mma_gemm<1>, cudaFuncAttributeMaxDynamicSharedMemorySize, GEMM_SMEM);
    cudaFuncSetAttribute(attn_mma_kernel, cudaFuncAttributeMaxDynamicSharedMemorySize, ATTN_SMEM);

    // all weight conversions in one launch; activations split
    wsplit_kernel<<<dim3(64, 64, 4), dim3(32, 8)>>>(Wq, Wk, Wv, Wo);
    asplit_kernel<<<(M_ * HID_ / 4) / 256, 256>>>(X);

    // fused QKV projection
    mma_gemm<1><<<dim3(48, M_ / 128), 256, GEMM_SMEM>>>(nullptr);

    rope_split_kernel<<<(B_ * H_ * S_ * 16) / 256, 256>>>(cosb, sinb);

    // attention: 64 q-rows per CTA, 128 threads, 2 CTAs/SM
    attn_mma_kernel<<<dim3(S_ / 64, B_ * H_), 128, ATTN_SMEM>>>();

    // O projection
    mma_gemm<0><<<dim3(HID_ / 128, M_ / 128), 256, GEMM_SMEM>>>(out);
}

// round 17
// speedup vs baseline: 1.0601x; 1.0012x over previous
#include <cuda_runtime.h>
#include <cuda_fp16.h>
#include <cstdint>

// ---------------------------------------------------------------------------
// Problem constants
// ---------------------------------------------------------------------------
#define B_ 2
#define S_ 2048
#define H_ 16
#define D_ 128
#define HID_ 2048
#define M_ (B_ * S_)   // 4096

// Scratch (device globals — allocation-free per harness rules)
__device__ float g_q[(size_t)B_ * H_ * S_ * D_];   // fp32 Q pre-rope [b,h,s,d]
__device__ float g_k[(size_t)B_ * H_ * S_ * D_];   // fp32 K pre-rope

// fp16 buffers. Activations split hi/lo; weights hi only (2-term emulation).
__device__ __half g_xhi[(size_t)M_ * HID_];
__device__ __half g_xlo[(size_t)M_ * HID_];
__device__ __half g_bhi[(size_t)4 * HID_ * HID_];

// fp16 attention operands [b,h,s,d]: Q split hi/lo; K, V hi only.
#define QKV_ELEMS ((size_t)B_ * H_ * S_ * D_)
__device__ __half g_qh[QKV_ELEMS];
__device__ __half g_ql[QKV_ELEMS];
__device__ __half g_kh[QKV_ELEMS];
__device__ __half g_vh[QKV_ELEMS];

// ---------------------------------------------------------------------------
// PTX helpers (non-'a' features only)
// ---------------------------------------------------------------------------
__device__ __forceinline__ uint32_t smem_u32(const void* p) {
    uint32_t a;
    asm("{ .reg .u64 t; cvta.to.shared.u64 t, %1; cvt.u32.u64 %0, t; }"
        : "=r"(a) : "l"(p));
    return a;
}
__device__ __forceinline__ void cpa16(uint32_t s, const void* g) {
    asm volatile("cp.async.cg.shared.global [%0], [%1], 16;" :: "r"(s), "l"(g));
}
#define CP_COMMIT() asm volatile("cp.async.commit_group;" ::: "memory")
#define CP_WAIT0()  asm volatile("cp.async.wait_group 0;" ::: "memory")
#define CP_WAIT1()  asm volatile("cp.async.wait_group 1;" ::: "memory")

#define LDSM4(r, addr)                                                        \
    asm volatile("ldmatrix.sync.aligned.m8n8.x4.shared.b16 {%0,%1,%2,%3}, [%4];" \
                 : "=r"((r)[0]), "=r"((r)[1]), "=r"((r)[2]), "=r"((r)[3])     \
                 : "r"(addr))
#define LDSM4T(r, addr)                                                       \
    asm volatile("ldmatrix.sync.aligned.m8n8.x4.trans.shared.b16 {%0,%1,%2,%3}, [%4];" \
                 : "=r"((r)[0]), "=r"((r)[1]), "=r"((r)[2]), "=r"((r)[3])     \
                 : "r"(addr))

#define MMAF32(d, a, b)                                                       \
    asm volatile(                                                             \
        "mma.sync.aligned.m16n8k16.row.col.f32.f16.f16.f32 "                  \
        "{%0,%1,%2,%3}, {%4,%5,%6,%7}, {%8,%9}, {%0,%1,%2,%3};"               \
        : "+f"((d)[0]), "+f"((d)[1]), "+f"((d)[2]), "+f"((d)[3])              \
        : "r"((a)[0]), "r"((a)[1]), "r"((a)[2]), "r"((a)[3]),                 \
          "r"((b)[0]), "r"((b)[1]))

__device__ __forceinline__ float2 h2f2(uint32_t u) {
    __half2 h = *(__half2*)&u;
    return __half22float2(h);
}
__device__ __forceinline__ uint32_t f2h2(float x, float y) {
    __half2 h = __float22half2_rn(make_float2(x, y));
    return *(uint32_t*)&h;
}

// fp32 -> fp16 hi/lo split
__device__ __forceinline__ void split1(float x, unsigned short& h, unsigned short& l) {
    __half hb = __float2half_rn(x);
    __half lb = __float2half_rn(x - __half2float(hb));
    h = __half_as_ushort(hb);
    l = __half_as_ushort(lb);
}

// ---------------------------------------------------------------------------
// Activations: X [M,K] fp32 -> g_xhi/g_xlo fp16.
// ---------------------------------------------------------------------------
__global__ void asplit_kernel(const float* __restrict__ src) {
    size_t i = (size_t)blockIdx.x * 256 + threadIdx.x;
    float4 v = ((const float4*)src)[i];
    ushort4 h, l;
    split1(v.x, h.x, l.x);
    split1(v.y, h.y, l.y);
    split1(v.z, h.z, l.z);
    split1(v.w, h.w, l.w);
    ((ushort4*)g_xhi)[i] = h;
    ((ushort4*)g_xlo)[i] = l;
}

// All 4 weights in one launch: W [K,N] fp32 -> g_bhi slot z, [N,K] fp16 hi.
__global__ void wsplit_kernel(const float* __restrict__ W0,
                              const float* __restrict__ W1,
                              const float* __restrict__ W2,
                              const float* __restrict__ W3) {
    __shared__ float ts[32][33];
    const int tx = threadIdx.x, ty = threadIdx.y;
    const int n0 = blockIdx.x * 32, k0 = blockIdx.y * 32;
    const int widx = blockIdx.z;
    const float* W = (widx == 0) ? W0 : (widx == 1) ? W1 : (widx == 2) ? W2 : W3;
    __half* bh = g_bhi + (size_t)widx * HID_ * HID_;
#pragma unroll
    for (int i = 0; i < 4; i++)
        ts[ty + 8 * i][tx] = W[(size_t)(k0 + ty + 8 * i) * HID_ + n0 + tx];
    __syncthreads();
#pragma unroll
    for (int i = 0; i < 4; i++) {
        int n = n0 + ty + 8 * i;
        int k = k0 + tx;
        bh[(size_t)n * HID_ + k] = __float2half_rn(ts[tx][ty + 8 * i]);
    }
}

// ---------------------------------------------------------------------------
// mma.sync fp16x2 GEMM (R13 config: 128x128, 256 threads, 2-stage, 2 CTA/SM)
// MODE==1: fused QKV (blockIdx.x = widx*16 + head). MODE==0: O projection.
// ---------------------------------------------------------------------------
#define PITCH 144
#define MATB  (128 * PITCH)          // 18432
#define BUFB  (3 * MATB)             // 55296 (Ah, Al, Bh)
#define GEMM_SMEM (2 * BUFB)         // 110592 -> two CTAs fit per SM
#define NCH (HID_ / 64)              // 32

template <int MODE>
__global__ __launch_bounds__(256, 2) void mma_gemm(float* __restrict__ Cout) {
    extern __shared__ char dsm[];
    const uint32_t sb = smem_u32(dsm);
    const int t = threadIdx.x;
    const int lane = t & 31, wid = t >> 5;
    const int wm = wid & 3, wn = wid >> 2;
    const int m0 = blockIdx.y * 128;
    const int widx = (MODE == 1) ? (blockIdx.x >> 4) : 3;
    const int nblk = (MODE == 1) ? (blockIdx.x & 15) : blockIdx.x;
    const int n0 = nblk * 128;

    const __half* __restrict__ AH = g_xhi;
    const __half* __restrict__ AL = g_xlo;
    const __half* __restrict__ BH = g_bhi + (size_t)widx * HID_ * HID_;

    float acc[2][8][4];
#pragma unroll
    for (int i = 0; i < 2; i++)
#pragma unroll
        for (int j = 0; j < 8; j++)
#pragma unroll
            for (int k = 0; k < 4; k++) acc[i][j][k] = 0.f;

    const int lrow = t >> 3;
    const int lch = t & 7;

    {
#pragma unroll
        for (int j = 0; j < 4; j++) {
            int row = lrow + j * 32;
            uint32_t sa = sb + row * PITCH + lch * 16;
            size_t ga = (size_t)(m0 + row) * HID_ + lch * 8;
            size_t gb = (size_t)(n0 + row) * HID_ + lch * 8;
            cpa16(sa, AH + ga);
            cpa16(sa + MATB, AL + ga);
            cpa16(sa + 2 * MATB, BH + gb);
        }
        CP_COMMIT();
    }

    const uint32_t lm_a_off =
        (uint32_t)((wm * 32 + (lane & 15)) * PITCH + (lane >> 4) * 16);
    const uint32_t lm_b_off =
        (uint32_t)((wn * 64 + (lane & 15)) * PITCH + (lane >> 4) * 16);

    for (int c = 0; c < NCH; c++) {
        CP_WAIT0();
        __syncthreads();

        if (c + 1 < NCH) {
            const uint32_t base = sb + ((c + 1) & 1) * BUFB;
            const int k0 = (c + 1) * 64;
#pragma unroll
            for (int j = 0; j < 4; j++) {
                int row = lrow + j * 32;
                uint32_t sa = base + row * PITCH + lch * 16;
                size_t ga = (size_t)(m0 + row) * HID_ + k0 + lch * 8;
                size_t gb = (size_t)(n0 + row) * HID_ + k0 + lch * 8;
                cpa16(sa, AH + ga);
                cpa16(sa + MATB, AL + ga);
                cpa16(sa + 2 * MATB, BH + gb);
            }
            CP_COMMIT();
        }

        const uint32_t cb = sb + (c & 1) * BUFB;
#pragma unroll
        for (int ks = 0; ks < 4; ks++) {
            uint32_t ah[2][4], al[2][4];
#pragma unroll
            for (int mt = 0; mt < 2; mt++) {
                uint32_t addr = cb + lm_a_off + mt * (16 * PITCH) + ks * 32;
                LDSM4(ah[mt], addr);
                LDSM4(al[mt], addr + MATB);
            }
            uint32_t bh[8][2];
#pragma unroll
            for (int np = 0; np < 4; np++) {
                uint32_t addr = cb + 2 * MATB + lm_b_off + np * (16 * PITCH) + ks * 32;
                uint32_t r[4];
                LDSM4(r, addr);
                bh[2 * np][0] = r[0]; bh[2 * np + 1][0] = r[1];
                bh[2 * np][1] = r[2]; bh[2 * np + 1][1] = r[3];
            }
#pragma unroll
            for (int mt = 0; mt < 2; mt++)
#pragma unroll
                for (int nt = 0; nt < 8; nt++)
                    MMAF32(acc[mt][nt], ah[mt], bh[nt]);
#pragma unroll
            for (int mt = 0; mt < 2; mt++)
#pragma unroll
                for (int nt = 0; nt < 8; nt++)
                    MMAF32(acc[mt][nt], al[mt], bh[nt]);
        }
    }

    const int qrow = lane >> 2;
    const int qcol = (lane & 3) * 2;
#pragma unroll
    for (int mt = 0; mt < 2; mt++) {
#pragma unroll
        for (int half_ = 0; half_ < 2; half_++) {
            const int m = m0 + wm * 32 + mt * 16 + qrow + half_ * 8;
            if (MODE == 1 && widx == 2) {
                int b_ = m >> 11, s_ = m & (S_ - 1);
                size_t base = (((size_t)b_ * H_ + nblk) * S_ + s_) * D_;
#pragma unroll
                for (int nt = 0; nt < 8; nt++) {
                    int col = wn * 64 + nt * 8 + qcol;
                    *(uint32_t*)(g_vh + base + col) =
                        f2h2(acc[mt][nt][half_ * 2], acc[mt][nt][half_ * 2 + 1]);
                }
            } else {
                float* dst;
                size_t base;
                if (MODE == 0) {
                    dst = Cout;
                    base = (size_t)m * HID_ + n0;
                } else {
                    int b_ = m >> 11, s_ = m & (S_ - 1);
                    dst = (widx == 0) ? g_q : g_k;
                    base = (((size_t)b_ * H_ + nblk) * S_ + s_) * D_;
                }
#pragma unroll
                for (int nt = 0; nt < 8; nt++) {
                    int col = wn * 64 + nt * 8 + qcol;
                    *(float2*)(dst + base + col) =
                        make_float2(acc[mt][nt][half_ * 2], acc[mt][nt][half_ * 2 + 1]);
                }
            }
        }
    }
}

// ---------------------------------------------------------------------------
// RoPE (vectorized, R16 — proven win).
// ---------------------------------------------------------------------------
__global__ void rope_split_kernel(const float* __restrict__ cosb,
                                  const float* __restrict__ sinb) {
    int tid = blockIdx.x * 256 + threadIdx.x;      // B_*H_*S_*16 threads
    int d = (tid & 15) * 4;                        // 0..60
    int s = (tid >> 4) & (S_ - 1);
    int bh = tid >> 15;
    size_t base = ((size_t)bh * S_ + s) * D_;

    float4 c0 = *(const float4*)(cosb + s * D_ + d);
    float4 c1 = *(const float4*)(cosb + s * D_ + d + 64);
    float4 s0 = *(const float4*)(sinb + s * D_ + d);
    float4 s1 = *(const float4*)(sinb + s * D_ + d + 64);
    float4 q0 = *(const float4*)(g_q + base + d);
    float4 q1 = *(const float4*)(g_q + base + d + 64);
    float4 k0 = *(const float4*)(g_k + base + d);
    float4 k1 = *(const float4*)(g_k + base + d + 64);

    float qa[4], qb[4], ka[4], kb[4];
    {
        const float* q0p = &q0.x; const float* q1p = &q1.x;
        const float* k0p = &k0.x; const float* k1p = &k1.x;
        const float* c0p = &c0.x; const float* c1p = &c1.x;
        const float* s0p = &s0.x; const float* s1p = &s1.x;
#pragma unroll
        for (int e = 0; e < 4; e++) {
            qa[e] = q0p[e] * c0p[e] - q1p[e] * s0p[e];
            qb[e] = q1p[e] * c1p[e] + q0p[e] * s1p[e];
            ka[e] = k0p[e] * c0p[e] - k1p[e] * s0p[e];
            kb[e] = k1p[e] * c1p[e] + k0p[e] * s1p[e];
        }
    }

    unsigned short h[4], l[4];
#pragma unroll
    for (int e = 0; e < 4; e++) split1(qa[e], h[e], l[e]);
    *(uint2*)(g_qh + base + d) = make_uint2(
        (uint32_t)h[0] | ((uint32_t)h[1] << 16), (uint32_t)h[2] | ((uint32_t)h[3] << 16));
    *(uint2*)(g_ql + base + d) = make_uint2(
        (uint32_t)l[0] | ((uint32_t)l[1] << 16), (uint32_t)l[2] | ((uint32_t)l[3] << 16));
#pragma unroll
    for (int e = 0; e < 4; e++) split1(qb[e], h[e], l[e]);
    *(uint2*)(g_qh + base + d + 64) = make_uint2(
        (uint32_t)h[0] | ((uint32_t)h[1] << 16), (uint32_t)h[2] | ((uint32_t)h[3] << 16));
    *(uint2*)(g_ql + base + d + 64) = make_uint2(
        (uint32_t)l[0] | ((uint32_t)l[1] << 16), (uint32_t)l[2] | ((uint32_t)l[3] << 16));

    *(uint2*)(g_kh + base + d) = make_uint2(
        f2h2(ka[0], ka[1]), f2h2(ka[2], ka[3]));
    *(uint2*)(g_kh + base + d + 64) = make_uint2(
        f2h2(kb[0], kb[1]), f2h2(kb[2], kb[3]));
}

// ---------------------------------------------------------------------------
// Flash attention: CTA = 64 q-rows, 128 threads, SINGLE-buffered 64-key K/V
// tiles -> 69.6KB SMEM -> 3 CTAs/SM (3 warps/SMSP; cross-CTA covers both the
// exposed loads and the softmax phase). Alpha-rescale skipped when no lane's
// running max changed (alpha == 1.0 exactly -> bit-identical).
// ---------------------------------------------------------------------------
#define AP    272
#define AMAT2 (64 * AP)               // 17408
#define ATTN_SMEM (4 * AMAT2)         // 69632
#define KT_   64
#define NKT   (S_ / KT_)              // 32

__global__ __launch_bounds__(128, 3) void attn_mma_kernel() {
    extern __shared__ char sm8[];
    const uint32_t sb = smem_u32(sm8);
    const uint32_t Qh = sb, Ql = sb + AMAT2;
    const uint32_t Kc = sb + 2 * AMAT2, Vc = sb + 3 * AMAT2;

    const int t = threadIdx.x, lane = t & 31, wid = t >> 5;
    const int bh = blockIdx.y;
    const int q0 = blockIdx.x * 64;
    const size_t qoff = ((size_t)bh * S_ + q0) * D_;
    const size_t koff = (size_t)bh * S_ * D_;

    const int lrow = t >> 4;
    const int lch = t & 15;

    // prologue: Q(hi,lo) + K0 + V0 in ONE group
    {
#pragma unroll
        for (int j = 0; j < 8; j++) {
            int row = lrow + j * 8;
            uint32_t so = (uint32_t)(row * AP + lch * 16);
            size_t gq = qoff + (size_t)row * D_ + lch * 8;
            size_t gk = koff + (size_t)row * D_ + lch * 8;
            cpa16(Qh + so, g_qh + gq);
            cpa16(Ql + so, g_ql + gq);
            cpa16(Kc + so, g_kh + gk);
            cpa16(Vc + so, g_vh + gk);
        }
        CP_COMMIT();
    }

    float sa[8][4];
    float oa[16][4];
#pragma unroll
    for (int i = 0; i < 16; i++)
#pragma unroll
        for (int j = 0; j < 4; j++) oa[i][j] = 0.f;
    float m0r = -1e30f, m1r = -1e30f, l0r = 0.f, l1r = 0.f;

    const float scale = 0.088388347648318447f;
    const uint32_t a_off =
        (uint32_t)((wid * 16 + (lane & 15)) * AP + (lane >> 4) * 16);
    const uint32_t lm_lo = (uint32_t)((lane & 15) * AP + (lane >> 4) * 16);

    for (int kt = 0; kt < NKT; kt++) {
        CP_WAIT0();           // tile kt resident (this thread's copies)
        __syncthreads();      // visibility across warps

#pragma unroll
        for (int i = 0; i < 8; i++)
#pragma unroll
            for (int j = 0; j < 4; j++) sa[i][j] = 0.f;

        // ---- S = Q K^T (64 keys) ----
#pragma unroll
        for (int ks = 0; ks < 8; ks++) {
            uint32_t qh[4], ql[4];
            LDSM4(qh, Qh + a_off + ks * 32);
            LDSM4(ql, Ql + a_off + ks * 32);
            uint32_t kA[4][2], kB[4][2];
#pragma unroll
            for (int np = 0; np < 4; np++) {
                uint32_t r[4];
                LDSM4(r, Kc + lm_lo + (uint32_t)(np * 16 * AP) + ks * 32);
                kA[np][0] = r[0]; kB[np][0] = r[1];
                kA[np][1] = r[2]; kB[np][1] = r[3];
            }
#pragma unroll
            for (int np = 0; np < 4; np++) {
                MMAF32(sa[2 * np], qh, kA[np]);
                MMAF32(sa[2 * np + 1], qh, kB[np]);
            }
#pragma unroll
            for (int np = 0; np < 4; np++) {
                MMAF32(sa[2 * np], ql, kA[np]);
                MMAF32(sa[2 * np + 1], ql, kB[np]);
            }
        }

        // ---- online softmax (alpha-skip when max unchanged) ----
        float rm0 = -1e30f, rm1 = -1e30f;
#pragma unroll
        for (int nt = 0; nt < 8; nt++) {
            rm0 = fmaxf(rm0, fmaxf(sa[nt][0], sa[nt][1]));
            rm1 = fmaxf(rm1, fmaxf(sa[nt][2], sa[nt][3]));
        }
#pragma unroll
        for (int off = 1; off <= 2; off <<= 1) {
            rm0 = fmaxf(rm0, __shfl_xor_sync(0xffffffffu, rm0, off));
            rm1 = fmaxf(rm1, __shfl_xor_sync(0xffffffffu, rm1, off));
        }
        float mn0 = fmaxf(m0r, rm0 * scale);
        float mn1 = fmaxf(m1r, rm1 * scale);
        bool ch = (mn0 != m0r) || (mn1 != m1r);
        if (__any_sync(0xffffffffu, ch)) {
            float al0 = __expf(m0r - mn0);
            float al1 = __expf(m1r - mn1);
            l0r *= al0;
            l1r *= al1;
#pragma unroll
            for (int nt = 0; nt < 16; nt++) {
                oa[nt][0] *= al0;
                oa[nt][1] *= al0;
                oa[nt][2] *= al1;
                oa[nt][3] *= al1;
            }
            m0r = mn0;
            m1r = mn1;
        }
        float rs0 = 0.f, rs1 = 0.f;
#pragma unroll
        for (int nt = 0; nt < 8; nt++) {
            float p0 = __expf(fmaf(sa[nt][0], scale, -m0r));
            float p1 = __expf(fmaf(sa[nt][1], scale, -m0r));
            float p2 = __expf(fmaf(sa[nt][2], scale, -m1r));
            float p3 = __expf(fmaf(sa[nt][3], scale, -m1r));
            sa[nt][0] = p0; sa[nt][1] = p1; sa[nt][2] = p2; sa[nt][3] = p3;
            rs0 += p0 + p1;
            rs1 += p2 + p3;
        }
#pragma unroll
        for (int off = 1; off <= 2; off <<= 1) {
            rs0 += __shfl_xor_sync(0xffffffffu, rs0, off);
            rs1 += __shfl_xor_sync(0xffffffffu, rs1, off);
        }
        l0r += rs0;
        l1r += rs1;

        // ---- O += P V ----
#pragma unroll
        for (int ks = 0; ks < 4; ks++) {
            uint32_t aH[4], aL[4];
#pragma unroll
            for (int g = 0; g < 2; g++) {
                const int tt = 2 * ks + g;
                float x0 = sa[tt][0], y0 = sa[tt][1];
                float x1 = sa[tt][2], y1 = sa[tt][3];
                uint32_t h0 = f2h2(x0, y0);
                uint32_t h1 = f2h2(x1, y1);
                float2 b0 = h2f2(h0);
                float2 b1 = h2f2(h1);
                aH[2 * g]     = h0;
                aH[2 * g + 1] = h1;
                aL[2 * g]     = f2h2(x0 - b0.x, y0 - b0.y);
                aL[2 * g + 1] = f2h2(x1 - b1.x, y1 - b1.y);
            }
            const uint32_t vbase = lm_lo + (uint32_t)(ks * 16 * AP);
#pragma unroll
            for (int h2 = 0; h2 < 2; h2++) {
                uint32_t vA[4][2], vB[4][2];
#pragma unroll
                for (int j = 0; j < 4; j++) {
                    const int np = h2 * 4 + j;
                    uint32_t r[4];
                    LDSM4T(r, Vc + vbase + np * 32);
                    vA[j][0] = r[0]; vA[j][1] = r[1];
                    vB[j][0] = r[2]; vB[j][1] = r[3];
                }
#pragma unroll
                for (int j = 0; j < 4; j++) {
                    const int np = h2 * 4 + j;
                    MMAF32(oa[2 * np], aH, vA[j]);
                    MMAF32(oa[2 * np + 1], aH, vB[j]);
                }
#pragma unroll
                for (int j = 0; j < 4; j++) {
                    const int np = h2 * 4 + j;
                    MMAF32(oa[2 * np], aL, vA[j]);
                    MMAF32(oa[2 * np + 1], aL, vB[j]);
                }
            }
        }

        // all warps done reading this tile -> safe to overwrite
        __syncthreads();
        if (kt + 1 < NKT) {
#pragma unroll
            for (int j = 0; j < 8; j++) {
                int row = lrow + j * 8;
                uint32_t so = (uint32_t)(row * AP + lch * 16);
                size_t gk = koff + (size_t)((kt + 1) * KT_ + row) * D_ + lch * 8;
                cpa16(Kc + so, g_kh + gk);
                cpa16(Vc + so, g_vh + gk);
            }
            CP_COMMIT();
        }
    }

    // ---- finalize: write xhi/xlo fp16 splits of attn output directly ----
    const int b_ = bh >> 4, h = bh & 15;
    const int row0 = q0 + wid * 16 + (lane >> 2);
    const float inv0 = 1.0f / l0r, inv1 = 1.0f / l1r;
    const size_t base0 = ((size_t)b_ * S_ + row0) * HID_ + h * D_;
    const size_t base1 = ((size_t)b_ * S_ + row0 + 8) * HID_ + h * D_;
    const int col0 = (lane & 3) * 2;
#pragma unroll
    for (int nt = 0; nt < 16; nt++) {
        int col = 8 * nt + col0;
        float x0 = oa[nt][0] * inv0, y0 = oa[nt][1] * inv0;
        float x1 = oa[nt][2] * inv1, y1 = oa[nt][3] * inv1;
        unsigned short hx, lx, hy, ly;
        split1(x0, hx, lx);
        split1(y0, hy, ly);
        *(uint32_t*)(g_xhi + base0 + col) = (uint32_t)hx | ((uint32_t)hy << 16);
        *(uint32_t*)(g_xlo + base0 + col) = (uint32_t)lx | ((uint32_t)ly << 16);
        split1(x1, hx, lx);
        split1(y1, hy, ly);
        *(uint32_t*)(g_xhi + base1 + col) = (uint32_t)hx | ((uint32_t)hy << 16);
        *(uint32_t*)(g_xlo + base1 + col) = (uint32_t)lx | ((uint32_t)ly << 16);
    }
}

// ---------------------------------------------------------------------------
// Launch
// ---------------------------------------------------------------------------
extern "C" void kernel_launch(void* const* d_in, const int* in_sizes, int n_in,
                              void* d_out, int out_size) {
    const float* X = (const float*)d_in[0];
    const float* cosb = (const float*)d_in[1];
    const float* sinb = (const float*)d_in[2];
    const float* Wq = (const float*)d_in[3];
    const float* Wk = (const float*)d_in[4];
    const float* Wv = (const float*)d_in[5];
    const float* Wo = (const float*)d_in[6];
    float* out = (float*)d_out;

    cudaFuncSetAttribute(mma_gemm<0>, cudaFuncAttributeMaxDynamicSharedMemorySize, GEMM_SMEM);
    cudaFuncSetAttribute(mma_gemm<1>, cudaFuncAttributeMaxDynamicSharedMemorySize, GEMM_SMEM);
    cudaFuncSetAttribute(attn_mma_kernel, cudaFuncAttributeMaxDynamicSharedMemorySize, ATTN_SMEM);

    // all weight conversions in one launch; activations split
    wsplit_kernel<<<dim3(64, 64, 4), dim3(32, 8)>>>(Wq, Wk, Wv, Wo);
    asplit_kernel<<<(M_ * HID_ / 4) / 256, 256>>>(X);

    // fused QKV projection
    mma_gemm<1><<<dim3(48, M_ / 128), 256, GEMM_SMEM>>>(nullptr);

    rope_split_kernel<<<(B_ * H_ * S_ * 16) / 256, 256>>>(cosb, sinb);

    // attention: 64 q-rows per CTA, 128 threads, 3 CTAs/SM
    attn_mma_kernel<<<dim3(S_ / 64, B_ * H_), 128, ATTN_SMEM>>>();

    // O projection
    mma_gemm<0><<<dim3(HID_ / 128, M_ / 128), 256, GEMM_SMEM>>>(out);
}